// round 1
// baseline (speedup 1.0000x reference)
#include <cuda_runtime.h>
#include <math.h>

// Problem constants
namespace {
constexpr int NRES  = 64;
constexpr int QD    = 512;
constexpr int KD    = 512;
constexpr int CIN   = 256;
constexpr int HEADS = 8;
constexpr int CH    = 32;
constexpr int HID   = 256;
constexpr int MTOT  = NRES * QD;                 // 32768
constexpr float QSCALE = 0.17677669529663687f;   // 1/sqrt(32)
}

// Scratch (static device globals; no runtime allocation)
__device__ float g_q  [(size_t)MTOT * HID];
__device__ float g_k  [(size_t)MTOT * HID];
__device__ float g_v  [(size_t)MTOT * HID];
__device__ float g_g  [(size_t)MTOT * HID];
__device__ float g_o  [(size_t)MTOT * HID];
__device__ float g_bpt[(size_t)HEADS * KD * QD]; // bias_pair transposed to [h][k][q]

// ---------------------------------------------------------------------------
// Tiled fp32 GEMM: C[M,256] = A[M,256] @ W[256,256]  (+ epilogue variants)
// MODE 0: plain           MODE 1: *QSCALE
// MODE 2: sigmoid(x+bias) MODE 3: A = A .* A2 (gate), epilogue +bias
// 128x128 tile, BK=8, 256 threads, 8x8 per-thread micro-tile.
// ---------------------------------------------------------------------------
template <int MODE>
__global__ __launch_bounds__(256)
void gemm_kernel(const float* __restrict__ A, const float* __restrict__ A2,
                 const float* __restrict__ W, const float* __restrict__ bias,
                 float* __restrict__ C)
{
    __shared__ float As[8][132];   // [k][m], padded to avoid store conflicts
    __shared__ float Bs[8][128];   // [k][n]

    const int t    = threadIdx.x;
    const int mblk = blockIdx.x * 128;
    const int nblk = blockIdx.y * 128;
    const int tx   = t & 15;       // 0..15 -> n micro
    const int ty   = t >> 4;       // 0..15 -> m micro

    const int arow = t >> 1;             // 0..127
    const int ac   = (t & 1) * 4;        // 0 or 4
    const int brow = t >> 5;             // 0..7
    const int bc   = (t & 31) * 4;       // 0..124

    float acc[8][8];
    #pragma unroll
    for (int i = 0; i < 8; i++)
        #pragma unroll
        for (int j = 0; j < 8; j++) acc[i][j] = 0.f;

    for (int k0 = 0; k0 < CIN; k0 += 8) {
        // load A tile (transposed into smem)
        float4 av = *(const float4*)(A + (size_t)(mblk + arow) * CIN + k0 + ac);
        if (MODE == 3) {
            float4 gv = *(const float4*)(A2 + (size_t)(mblk + arow) * CIN + k0 + ac);
            av.x *= gv.x; av.y *= gv.y; av.z *= gv.z; av.w *= gv.w;
        }
        As[ac + 0][arow] = av.x;
        As[ac + 1][arow] = av.y;
        As[ac + 2][arow] = av.z;
        As[ac + 3][arow] = av.w;

        // load B tile
        float4 bv = *(const float4*)(W + (size_t)(k0 + brow) * HID + nblk + bc);
        *(float4*)&Bs[brow][bc] = bv;

        __syncthreads();

        #pragma unroll
        for (int kk = 0; kk < 8; kk++) {
            float4 a0 = *(const float4*)&As[kk][ty * 8];
            float4 a1 = *(const float4*)&As[kk][ty * 8 + 4];
            float4 b0 = *(const float4*)&Bs[kk][tx * 8];
            float4 b1 = *(const float4*)&Bs[kk][tx * 8 + 4];
            float a[8] = {a0.x, a0.y, a0.z, a0.w, a1.x, a1.y, a1.z, a1.w};
            float b[8] = {b0.x, b0.y, b0.z, b0.w, b1.x, b1.y, b1.z, b1.w};
            #pragma unroll
            for (int i = 0; i < 8; i++)
                #pragma unroll
                for (int j = 0; j < 8; j++)
                    acc[i][j] += a[i] * b[j];
        }
        __syncthreads();
    }

    // epilogue
    #pragma unroll
    for (int i = 0; i < 8; i++) {
        const int row = mblk + ty * 8 + i;
        #pragma unroll
        for (int j0 = 0; j0 < 8; j0 += 4) {
            const int col = nblk + tx * 8 + j0;
            float4 v;
            v.x = acc[i][j0 + 0];
            v.y = acc[i][j0 + 1];
            v.z = acc[i][j0 + 2];
            v.w = acc[i][j0 + 3];
            if (MODE == 1) {
                v.x *= QSCALE; v.y *= QSCALE; v.z *= QSCALE; v.w *= QSCALE;
            } else if (MODE == 2) {
                v.x = 1.f / (1.f + __expf(-(v.x + bias[col + 0])));
                v.y = 1.f / (1.f + __expf(-(v.y + bias[col + 1])));
                v.z = 1.f / (1.f + __expf(-(v.z + bias[col + 2])));
                v.w = 1.f / (1.f + __expf(-(v.w + bias[col + 3])));
            } else if (MODE == 3) {
                v.x += bias[col + 0];
                v.y += bias[col + 1];
                v.z += bias[col + 2];
                v.w += bias[col + 3];
            }
            *(float4*)(C + (size_t)row * HID + col) = v;
        }
    }
}

// ---------------------------------------------------------------------------
// Transpose bias_pair [H][Q][K] -> [H][K][Q] for coalesced per-key access
// ---------------------------------------------------------------------------
__global__ void transpose_bp_kernel(const float* __restrict__ bp, float* __restrict__ bpt)
{
    __shared__ float tile[32][33];
    const int h  = blockIdx.z;
    const int k0 = blockIdx.x * 32;
    const int q0 = blockIdx.y * 32;

    for (int j = threadIdx.y; j < 32; j += 8)
        tile[j][threadIdx.x] = bp[((size_t)h * QD + q0 + j) * KD + k0 + threadIdx.x];
    __syncthreads();
    for (int j = threadIdx.y; j < 32; j += 8)
        bpt[((size_t)h * KD + k0 + j) * QD + q0 + threadIdx.x] = tile[threadIdx.x][j];
}

// ---------------------------------------------------------------------------
// Attention: one block per (h, n). K/V head slices live in SMEM (64KB each).
// Each of 512 threads owns one q-row: flash-style online softmax, no
// cross-thread reductions. Writes un-gated O (gating fused into out-proj).
// ---------------------------------------------------------------------------
__global__ __launch_bounds__(512)
void attn_kernel(const float* __restrict__ q, const float* __restrict__ kin,
                 const float* __restrict__ vin, const float* __restrict__ bmask,
                 const float* __restrict__ bpt, float* __restrict__ o)
{
    extern __shared__ float sm[];
    float* ks  = sm;                 // KD*CH
    float* vs  = sm + KD * CH;       // KD*CH
    float* bms = sm + 2 * KD * CH;   // KD

    const int h = blockIdx.x;
    const int n = blockIdx.y;
    const int t = threadIdx.x;       // 0..511 == q row

    // stage K and V head slices into smem
    const float* kb = kin + (size_t)n * KD * HID + h * CH;
    const float* vb = vin + (size_t)n * KD * HID + h * CH;
    for (int idx = t; idx < KD * (CH / 4); idx += 512) {
        const int row = idx >> 3;
        const int c   = (idx & 7) << 2;
        *(float4*)(ks + row * CH + c) = *(const float4*)(kb + (size_t)row * HID + c);
        *(float4*)(vs + row * CH + c) = *(const float4*)(vb + (size_t)row * HID + c);
    }
    bms[t] = bmask[(size_t)n * KD + t];   // KD == blockDim == 512
    __syncthreads();

    const int row = t;
    float qr[CH];
    {
        const float* qb = q + ((size_t)n * QD + row) * HID + h * CH;
        #pragma unroll
        for (int i = 0; i < CH; i += 4) {
            float4 v4 = *(const float4*)(qb + i);
            qr[i] = v4.x; qr[i + 1] = v4.y; qr[i + 2] = v4.z; qr[i + 3] = v4.w;
        }
    }

    float acc[CH];
    #pragma unroll
    for (int i = 0; i < CH; i++) acc[i] = 0.f;
    float m = -1e30f, l = 0.f;

    const float* bpr = bpt + (size_t)h * KD * QD + row;   // + kk*QD
    float bnx = bpr[0];

    for (int kk = 0; kk < KD; kk++) {
        const float bcur = bnx;
        bnx = (kk + 1 < KD) ? bpr[(size_t)(kk + 1) * QD] : 0.f;

        // dot(q_row, k_row) with 4 partial sums
        const float* krow = ks + kk * CH;
        float s0 = 0.f, s1 = 0.f, s2 = 0.f, s3 = 0.f;
        #pragma unroll
        for (int i = 0; i < CH; i += 4) {
            float4 kv = *(const float4*)(krow + i);
            s0 += qr[i]     * kv.x;
            s1 += qr[i + 1] * kv.y;
            s2 += qr[i + 2] * kv.z;
            s3 += qr[i + 3] * kv.w;
        }
        float s = (s0 + s1) + (s2 + s3) + bms[kk] + bcur;

        if (s > m) {                       // rare (~ln(K) times per row)
            const float corr = __expf(m - s);
            m = s;
            l *= corr;
            #pragma unroll
            for (int i = 0; i < CH; i++) acc[i] *= corr;
        }
        const float p = __expf(s - m);
        l += p;
        const float* vrow = vs + kk * CH;
        #pragma unroll
        for (int i = 0; i < CH; i += 4) {
            float4 vv = *(const float4*)(vrow + i);
            acc[i]     += p * vv.x;
            acc[i + 1] += p * vv.y;
            acc[i + 2] += p * vv.z;
            acc[i + 3] += p * vv.w;
        }
    }

    const float inv = 1.f / l;
    float* ob = o + ((size_t)n * QD + row) * HID + h * CH;
    #pragma unroll
    for (int i = 0; i < CH; i += 4) {
        float4 r;
        r.x = acc[i] * inv; r.y = acc[i + 1] * inv;
        r.z = acc[i + 2] * inv; r.w = acc[i + 3] * inv;
        *(float4*)(ob + i) = r;
    }
}

// ---------------------------------------------------------------------------
extern "C" void kernel_launch(void* const* d_in, const int* in_sizes, int n_in,
                              void* d_out, int out_size)
{
    const float* q_x       = (const float*)d_in[0];
    const float* k_x       = (const float*)d_in[1];
    const float* v_x       = (const float*)d_in[2];
    const float* bias_mask = (const float*)d_in[3];
    const float* bias_pair = (const float*)d_in[4];
    const float* wq        = (const float*)d_in[5];
    const float* wk        = (const float*)d_in[6];
    const float* wv        = (const float*)d_in[7];
    const float* wg        = (const float*)d_in[8];
    const float* bg        = (const float*)d_in[9];
    const float* wo        = (const float*)d_in[10];
    const float* bo        = (const float*)d_in[11];
    float* out             = (float*)d_out;

    float *pq, *pk, *pv, *pg, *po, *pbpt;
    cudaGetSymbolAddress((void**)&pq,   g_q);
    cudaGetSymbolAddress((void**)&pk,   g_k);
    cudaGetSymbolAddress((void**)&pv,   g_v);
    cudaGetSymbolAddress((void**)&pg,   g_g);
    cudaGetSymbolAddress((void**)&po,   g_o);
    cudaGetSymbolAddress((void**)&pbpt, g_bpt);

    // bias_pair transpose [H,Q,K] -> [H,K,Q]
    {
        dim3 grid(KD / 32, QD / 32, HEADS), blk(32, 8);
        transpose_bp_kernel<<<grid, blk>>>(bias_pair, pbpt);
    }

    // projections
    {
        dim3 grid(MTOT / 128, HID / 128), blk(256);
        gemm_kernel<1><<<grid, blk>>>(q_x, nullptr, wq, nullptr, pq);   // q (scaled)
        gemm_kernel<0><<<grid, blk>>>(k_x, nullptr, wk, nullptr, pk);   // k
        gemm_kernel<0><<<grid, blk>>>(v_x, nullptr, wv, nullptr, pv);   // v
        gemm_kernel<2><<<grid, blk>>>(q_x, nullptr, wg, bg,      pg);   // gate
    }

    // attention
    {
        const int smem = (2 * KD * CH + KD) * (int)sizeof(float);  // 130 KB
        static bool attr_set = false;
        if (!attr_set) {
            cudaFuncSetAttribute(attn_kernel,
                                 cudaFuncAttributeMaxDynamicSharedMemorySize, smem);
            attr_set = true;
        }
        dim3 grid(HEADS, NRES), blk(512);
        attn_kernel<<<grid, blk, smem>>>(pq, pk, pv, bias_mask, pbpt, po);
    }

    // gated output projection -> d_out
    {
        dim3 grid(MTOT / 128, HID / 128), blk(256);
        gemm_kernel<3><<<grid, blk>>>(po, pg, wo, bo, out);
    }
}

// round 4
// speedup vs baseline: 1.2959x; 1.2959x over previous
#include <cuda_runtime.h>
#include <math.h>
#include <stdint.h>

// ---------------------------------------------------------------------------
// Problem constants
// ---------------------------------------------------------------------------
namespace {
constexpr int NRES  = 64;
constexpr int QD    = 512;
constexpr int KD    = 512;
constexpr int CIN   = 256;
constexpr int HEADS = 8;
constexpr int CH    = 32;
constexpr int HID   = 256;
constexpr int MTOT  = NRES * QD;                 // 32768
constexpr float QSCALE = 0.17677669529663687f;   // 1/sqrt(32)

// GEMM tiling
constexpr int BM = 128, BN = 128, BK = 16;
constexpr int LDP = 136;                         // 128 + 8 pad -> conflict-free frags
}

// Scratch (static device globals; no runtime allocation)
__device__ float g_q  [(size_t)MTOT * HID];
__device__ float g_k  [(size_t)MTOT * HID];
__device__ float g_v  [(size_t)MTOT * HID];
__device__ float g_g  [(size_t)MTOT * HID];
__device__ float g_o  [(size_t)MTOT * HID];
__device__ float g_bpt[(size_t)HEADS * KD * QD]; // bias_pair transposed [h][k][q]
__device__ float g_wt [5 * CIN * HID];           // transposed weights [n][k]

// ---------------------------------------------------------------------------
// helpers
// ---------------------------------------------------------------------------
__device__ __forceinline__ uint32_t f2tf32(float x) {
    uint32_t u;
    asm("cvt.rna.tf32.f32 %0, %1;" : "=r"(u) : "f"(x));
    return u;
}

// D += A * B  (m16n8k8, tf32 in, f32 accum)
__device__ __forceinline__ void mma1688(float* c, const uint32_t* a, const uint32_t* b) {
    asm volatile(
        "mma.sync.aligned.m16n8k8.row.col.f32.tf32.tf32.f32 "
        "{%0,%1,%2,%3}, {%4,%5,%6,%7}, {%8,%9}, {%0,%1,%2,%3};"
        : "+f"(c[0]), "+f"(c[1]), "+f"(c[2]), "+f"(c[3])
        : "r"(a[0]), "r"(a[1]), "r"(a[2]), "r"(a[3]), "r"(b[0]), "r"(b[1]));
}

template <int MODE>
__device__ __forceinline__ float epi(float x, const float* __restrict__ bias, int col) {
    if (MODE == 1) return x * QSCALE;
    if (MODE == 2) return 1.f / (1.f + __expf(-(x + bias[col])));
    if (MODE == 3) return x + bias[col];
    return x;
}

// ---------------------------------------------------------------------------
// tf32 mma.sync GEMM: C[M,256] = A[M,256] @ Wt^T   (Wt stored [n][k])
// CTA tile 128x128x16, 8 warps (2x4), warp tile 64x32, double-buffered smem.
// MODE 0: plain  1: *QSCALE  2: sigmoid(x+bias)  3: A=A.*A2, epi +bias
// ---------------------------------------------------------------------------
template <int MODE>
__global__ __launch_bounds__(256, 2)
void gemm_mma(const float* __restrict__ A, const float* __restrict__ A2,
              const float* __restrict__ Wt, const float* __restrict__ bias,
              float* __restrict__ C)
{
    __shared__ uint32_t As[2][BK][LDP];
    __shared__ uint32_t Bs[2][BK][LDP];

    const int tid  = threadIdx.x;
    const int lane = tid & 31;
    const int w    = tid >> 5;
    const int g    = lane >> 2;     // 0..7
    const int t4   = lane & 3;      // 0..3
    const int wm   = (w >> 2) * 64; // 0 / 64
    const int wn   = (w & 3) * 32;  // 0..96
    const int mblk = blockIdx.x * BM;
    const int nblk = blockIdx.y * BN;

    const int lm = tid >> 2;        // 0..63 (row within half-tile)
    const int lk = (tid & 3) * 4;   // 0,4,8,12

    float acc[4][4][4];
    #pragma unroll
    for (int i = 0; i < 4; i++)
        #pragma unroll
        for (int j = 0; j < 4; j++)
            #pragma unroll
            for (int r = 0; r < 4; r++) acc[i][j][r] = 0.f;

    float4 va[2], ga[2], vb[2];

    auto LOAD = [&](int bk) {
        const int k0 = bk * BK;
        #pragma unroll
        for (int r = 0; r < 2; r++) {
            const int m = lm + r * 64;
            va[r] = *(const float4*)(A  + (size_t)(mblk + m) * CIN + k0 + lk);
            if (MODE == 3)
                ga[r] = *(const float4*)(A2 + (size_t)(mblk + m) * CIN + k0 + lk);
            vb[r] = *(const float4*)(Wt + (size_t)(nblk + m) * CIN + k0 + lk);
        }
    };
    auto STS = [&](int buf) {
        #pragma unroll
        for (int r = 0; r < 2; r++) {
            const int m = lm + r * 64;
            float4 v = va[r];
            if (MODE == 3) {
                v.x *= ga[r].x; v.y *= ga[r].y; v.z *= ga[r].z; v.w *= ga[r].w;
            }
            As[buf][lk + 0][m] = f2tf32(v.x);
            As[buf][lk + 1][m] = f2tf32(v.y);
            As[buf][lk + 2][m] = f2tf32(v.z);
            As[buf][lk + 3][m] = f2tf32(v.w);
            const float4 b = vb[r];
            Bs[buf][lk + 0][m] = f2tf32(b.x);
            Bs[buf][lk + 1][m] = f2tf32(b.y);
            Bs[buf][lk + 2][m] = f2tf32(b.z);
            Bs[buf][lk + 3][m] = f2tf32(b.w);
        }
    };
    auto COMP = [&](int buf) {
        #pragma unroll
        for (int s = 0; s < 2; s++) {
            const int kb = s * 8;
            uint32_t af[4][4], bf[4][2];
            #pragma unroll
            for (int mt = 0; mt < 4; mt++) {
                const int m = wm + mt * 16 + g;
                af[mt][0] = As[buf][kb + t4    ][m];
                af[mt][1] = As[buf][kb + t4    ][m + 8];
                af[mt][2] = As[buf][kb + t4 + 4][m];
                af[mt][3] = As[buf][kb + t4 + 4][m + 8];
            }
            #pragma unroll
            for (int nt = 0; nt < 4; nt++) {
                const int n = wn + nt * 8 + g;
                bf[nt][0] = Bs[buf][kb + t4    ][n];
                bf[nt][1] = Bs[buf][kb + t4 + 4][n];
            }
            #pragma unroll
            for (int mt = 0; mt < 4; mt++)
                #pragma unroll
                for (int nt = 0; nt < 4; nt++)
                    mma1688(acc[mt][nt], af[mt], bf[nt]);
        }
    };

    LOAD(0);
    STS(0);
    __syncthreads();

    for (int bk = 0; bk < CIN / BK; bk++) {
        const int buf = bk & 1;
        if (bk < CIN / BK - 1) LOAD(bk + 1);
        COMP(buf);
        if (bk < CIN / BK - 1) {
            __syncthreads();
            STS(buf ^ 1);
            __syncthreads();
        }
    }

    // epilogue
    #pragma unroll
    for (int mt = 0; mt < 4; mt++) {
        const int row = mblk + wm + mt * 16 + g;
        #pragma unroll
        for (int nt = 0; nt < 4; nt++) {
            const int col = nblk + wn + nt * 8 + 2 * t4;
            float2 v01, v23;
            v01.x = epi<MODE>(acc[mt][nt][0], bias, col);
            v01.y = epi<MODE>(acc[mt][nt][1], bias, col + 1);
            v23.x = epi<MODE>(acc[mt][nt][2], bias, col);
            v23.y = epi<MODE>(acc[mt][nt][3], bias, col + 1);
            *(float2*)(C + (size_t)row * HID + col)       = v01;
            *(float2*)(C + (size_t)(row + 8) * HID + col) = v23;
        }
    }
}

// ---------------------------------------------------------------------------
// 256x256 transpose: dst[n][k] = src[k][n]
// ---------------------------------------------------------------------------
__global__ void transpose_w_kernel(const float* __restrict__ src, float* __restrict__ dst)
{
    __shared__ float tile[32][33];
    const int k0 = blockIdx.x * 32;
    const int n0 = blockIdx.y * 32;
    for (int j = threadIdx.y; j < 32; j += 8)
        tile[j][threadIdx.x] = src[(size_t)(k0 + j) * HID + n0 + threadIdx.x];
    __syncthreads();
    for (int j = threadIdx.y; j < 32; j += 8)
        dst[(size_t)(n0 + j) * CIN + k0 + threadIdx.x] = tile[threadIdx.x][j];
}

// ---------------------------------------------------------------------------
// Transpose bias_pair [H][Q][K] -> [H][K][Q]
// ---------------------------------------------------------------------------
__global__ void transpose_bp_kernel(const float* __restrict__ bp, float* __restrict__ bpt)
{
    __shared__ float tile[32][33];
    const int h  = blockIdx.z;
    const int k0 = blockIdx.x * 32;
    const int q0 = blockIdx.y * 32;
    for (int j = threadIdx.y; j < 32; j += 8)
        tile[j][threadIdx.x] = bp[((size_t)h * QD + q0 + j) * KD + k0 + threadIdx.x];
    __syncthreads();
    for (int j = threadIdx.y; j < 32; j += 8)
        bpt[((size_t)h * KD + k0 + j) * QD + q0 + threadIdx.x] = tile[threadIdx.x][j];
}

// ---------------------------------------------------------------------------
// Attention (fp32): one block per (h, n); thread = q row; online softmax.
// ---------------------------------------------------------------------------
__global__ __launch_bounds__(512)
void attn_kernel(const float* __restrict__ q, const float* __restrict__ kin,
                 const float* __restrict__ vin, const float* __restrict__ bmask,
                 const float* __restrict__ bpt, float* __restrict__ o)
{
    extern __shared__ float smf[];
    float* ks  = smf;
    float* vs  = smf + KD * CH;
    float* bms = smf + 2 * KD * CH;

    const int h = blockIdx.x;
    const int n = blockIdx.y;
    const int t = threadIdx.x;

    const float* kb = kin + (size_t)n * KD * HID + h * CH;
    const float* vb = vin + (size_t)n * KD * HID + h * CH;
    for (int idx = t; idx < KD * (CH / 4); idx += 512) {
        const int row = idx >> 3;
        const int c   = (idx & 7) << 2;
        *(float4*)(ks + row * CH + c) = *(const float4*)(kb + (size_t)row * HID + c);
        *(float4*)(vs + row * CH + c) = *(const float4*)(vb + (size_t)row * HID + c);
    }
    bms[t] = bmask[(size_t)n * KD + t];
    __syncthreads();

    const int row = t;
    float qr[CH];
    {
        const float* qb = q + ((size_t)n * QD + row) * HID + h * CH;
        #pragma unroll
        for (int i = 0; i < CH; i += 4) {
            float4 v4 = *(const float4*)(qb + i);
            qr[i] = v4.x; qr[i + 1] = v4.y; qr[i + 2] = v4.z; qr[i + 3] = v4.w;
        }
    }

    float acc[CH];
    #pragma unroll
    for (int i = 0; i < CH; i++) acc[i] = 0.f;
    float m = -1e30f, l = 0.f;

    const float* bpr = bpt + (size_t)h * KD * QD + row;
    float bnx = bpr[0];

    for (int kk = 0; kk < KD; kk++) {
        const float bcur = bnx;
        bnx = (kk + 1 < KD) ? bpr[(size_t)(kk + 1) * QD] : 0.f;

        const float* krow = ks + kk * CH;
        float s0 = 0.f, s1 = 0.f, s2 = 0.f, s3 = 0.f;
        #pragma unroll
        for (int i = 0; i < CH; i += 4) {
            float4 kv = *(const float4*)(krow + i);
            s0 += qr[i]     * kv.x;
            s1 += qr[i + 1] * kv.y;
            s2 += qr[i + 2] * kv.z;
            s3 += qr[i + 3] * kv.w;
        }
        float s = (s0 + s1) + (s2 + s3) + bms[kk] + bcur;

        if (s > m) {
            const float corr = __expf(m - s);
            m = s;
            l *= corr;
            #pragma unroll
            for (int i = 0; i < CH; i++) acc[i] *= corr;
        }
        const float p = __expf(s - m);
        l += p;
        const float* vrow = vs + kk * CH;
        #pragma unroll
        for (int i = 0; i < CH; i += 4) {
            float4 vv = *(const float4*)(vrow + i);
            acc[i]     += p * vv.x;
            acc[i + 1] += p * vv.y;
            acc[i + 2] += p * vv.z;
            acc[i + 3] += p * vv.w;
        }
    }

    const float inv = 1.f / l;
    float* ob = o + ((size_t)n * QD + row) * HID + h * CH;
    #pragma unroll
    for (int i = 0; i < CH; i += 4) {
        float4 r;
        r.x = acc[i] * inv; r.y = acc[i + 1] * inv;
        r.z = acc[i + 2] * inv; r.w = acc[i + 3] * inv;
        *(float4*)(ob + i) = r;
    }
}

// ---------------------------------------------------------------------------
extern "C" void kernel_launch(void* const* d_in, const int* in_sizes, int n_in,
                              void* d_out, int out_size)
{
    const float* q_x       = (const float*)d_in[0];
    const float* k_x       = (const float*)d_in[1];
    const float* v_x       = (const float*)d_in[2];
    const float* bias_mask = (const float*)d_in[3];
    const float* bias_pair = (const float*)d_in[4];
    const float* wq        = (const float*)d_in[5];
    const float* wk        = (const float*)d_in[6];
    const float* wv        = (const float*)d_in[7];
    const float* wg        = (const float*)d_in[8];
    const float* bg        = (const float*)d_in[9];
    const float* wo        = (const float*)d_in[10];
    const float* bo        = (const float*)d_in[11];
    float* out             = (float*)d_out;

    float *pq, *pk, *pv, *pg, *po, *pbpt, *pwt;
    cudaGetSymbolAddress((void**)&pq,   g_q);
    cudaGetSymbolAddress((void**)&pk,   g_k);
    cudaGetSymbolAddress((void**)&pv,   g_v);
    cudaGetSymbolAddress((void**)&pg,   g_g);
    cudaGetSymbolAddress((void**)&po,   g_o);
    cudaGetSymbolAddress((void**)&pbpt, g_bpt);
    cudaGetSymbolAddress((void**)&pwt,  g_wt);

    static bool attr_set = false;
    if (!attr_set) {
        cudaFuncSetAttribute(attn_kernel, cudaFuncAttributeMaxDynamicSharedMemorySize,
                             (2 * KD * CH + KD) * (int)sizeof(float));
        attr_set = true;
    }

    // transposes: bias_pair and the 5 weights
    {
        dim3 grid(KD / 32, QD / 32, HEADS), blk(32, 8);
        transpose_bp_kernel<<<grid, blk>>>(bias_pair, pbpt);
        dim3 gw(CIN / 32, HID / 32), bw(32, 8);
        transpose_w_kernel<<<gw, bw>>>(wq, pwt + 0 * CIN * HID);
        transpose_w_kernel<<<gw, bw>>>(wk, pwt + 1 * CIN * HID);
        transpose_w_kernel<<<gw, bw>>>(wv, pwt + 2 * CIN * HID);
        transpose_w_kernel<<<gw, bw>>>(wg, pwt + 3 * CIN * HID);
        transpose_w_kernel<<<gw, bw>>>(wo, pwt + 4 * CIN * HID);
    }

    // projections (tf32 mma.sync)
    {
        dim3 grid(MTOT / BM, HID / BN), blk(256);
        gemm_mma<1><<<grid, blk>>>(q_x, nullptr, pwt + 0 * CIN * HID, nullptr, pq);
        gemm_mma<0><<<grid, blk>>>(k_x, nullptr, pwt + 1 * CIN * HID, nullptr, pk);
        gemm_mma<0><<<grid, blk>>>(v_x, nullptr, pwt + 2 * CIN * HID, nullptr, pv);
        gemm_mma<2><<<grid, blk>>>(q_x, nullptr, pwt + 3 * CIN * HID, bg,      pg);
    }

    // attention (fp32)
    {
        const int smem = (2 * KD * CH + KD) * (int)sizeof(float);
        dim3 grid(HEADS, NRES), blk(512);
        attn_kernel<<<grid, blk, smem>>>(pq, pk, pv, bias_mask, pbpt, po);
    }

    // gated output projection -> d_out (tf32 mma.sync)
    {
        dim3 grid(MTOT / BM, HID / BN), blk(256);
        gemm_mma<3><<<grid, blk>>>(po, pg, pwt + 4 * CIN * HID, bo, out);
    }
}

// round 5
// speedup vs baseline: 2.0208x; 1.5593x over previous
#include <cuda_runtime.h>
#include <math.h>
#include <stdint.h>

// ---------------------------------------------------------------------------
// Problem constants
// ---------------------------------------------------------------------------
namespace {
constexpr int NRES  = 64;
constexpr int QD    = 512;
constexpr int KD    = 512;
constexpr int CIN   = 256;
constexpr int HEADS = 8;
constexpr int CH    = 32;
constexpr int HID   = 256;
constexpr int MTOT  = NRES * QD;                 // 32768
constexpr float QSCALE = 0.17677669529663687f;   // 1/sqrt(32)
constexpr float LOG2E  = 1.4426950408889634f;

// GEMM tiling
constexpr int BM = 128, BN = 128, BK = 16;
constexpr int LDP = 136;                         // 128 + 8 pad -> conflict-free frags
}

// Scratch (static device globals; no runtime allocation)
__device__ float g_q  [(size_t)MTOT * HID];
__device__ float g_k  [(size_t)MTOT * HID];
__device__ float g_v  [(size_t)MTOT * HID];
__device__ float g_g  [(size_t)MTOT * HID];
__device__ float g_o  [(size_t)MTOT * HID];
__device__ float g_wt [5 * CIN * HID];           // transposed weights [n][k]

// ---------------------------------------------------------------------------
// helpers
// ---------------------------------------------------------------------------
__device__ __forceinline__ uint32_t f2tf32(float x) {
    uint32_t u;
    asm("cvt.rna.tf32.f32 %0, %1;" : "=r"(u) : "f"(x));
    return u;
}

// D += A * B  (m16n8k8, tf32 in, f32 accum)
__device__ __forceinline__ void mma1688(float* c, const uint32_t* a, const uint32_t* b) {
    asm volatile(
        "mma.sync.aligned.m16n8k8.row.col.f32.tf32.tf32.f32 "
        "{%0,%1,%2,%3}, {%4,%5,%6,%7}, {%8,%9}, {%0,%1,%2,%3};"
        : "+f"(c[0]), "+f"(c[1]), "+f"(c[2]), "+f"(c[3])
        : "r"(a[0]), "r"(a[1]), "r"(a[2]), "r"(a[3]), "r"(b[0]), "r"(b[1]));
}

// ---------------------------------------------------------------------------
// tf32 mma.sync GEMM core (templated epilogue)
// CTA tile 128x128x16, 8 warps (2x4), warp tile 64x32, double-buffered smem.
// MODE 0: plain  1: *QSCALE  2: sigmoid(x+bias)  3: A=A.*A2, epi +bias
// ---------------------------------------------------------------------------
template <int MODE>
__device__ __forceinline__
void gemm_core(const float* __restrict__ A, const float* __restrict__ A2,
               const float* __restrict__ Wt, const float* __restrict__ bias,
               float* __restrict__ C, int mblk, int nblk)
{
    __shared__ uint32_t As[2][BK][LDP];
    __shared__ uint32_t Bs[2][BK][LDP];

    const int tid  = threadIdx.x;
    const int lane = tid & 31;
    const int w    = tid >> 5;
    const int g    = lane >> 2;
    const int t4   = lane & 3;
    const int wm   = (w >> 2) * 64;
    const int wn   = (w & 3) * 32;

    const int lm = tid >> 2;
    const int lk = (tid & 3) * 4;

    float acc[4][4][4];
    #pragma unroll
    for (int i = 0; i < 4; i++)
        #pragma unroll
        for (int j = 0; j < 4; j++)
            #pragma unroll
            for (int r = 0; r < 4; r++) acc[i][j][r] = 0.f;

    float4 va[2], ga[2], vb[2];

    auto LOAD = [&](int bk) {
        const int k0 = bk * BK;
        #pragma unroll
        for (int r = 0; r < 2; r++) {
            const int m = lm + r * 64;
            va[r] = *(const float4*)(A  + (size_t)(mblk + m) * CIN + k0 + lk);
            if (MODE == 3)
                ga[r] = *(const float4*)(A2 + (size_t)(mblk + m) * CIN + k0 + lk);
            vb[r] = *(const float4*)(Wt + (size_t)(nblk + m) * CIN + k0 + lk);
        }
    };
    auto STS = [&](int buf) {
        #pragma unroll
        for (int r = 0; r < 2; r++) {
            const int m = lm + r * 64;
            float4 v = va[r];
            if (MODE == 3) {
                v.x *= ga[r].x; v.y *= ga[r].y; v.z *= ga[r].z; v.w *= ga[r].w;
            }
            As[buf][lk + 0][m] = f2tf32(v.x);
            As[buf][lk + 1][m] = f2tf32(v.y);
            As[buf][lk + 2][m] = f2tf32(v.z);
            As[buf][lk + 3][m] = f2tf32(v.w);
            const float4 b = vb[r];
            Bs[buf][lk + 0][m] = f2tf32(b.x);
            Bs[buf][lk + 1][m] = f2tf32(b.y);
            Bs[buf][lk + 2][m] = f2tf32(b.z);
            Bs[buf][lk + 3][m] = f2tf32(b.w);
        }
    };
    auto COMP = [&](int buf) {
        #pragma unroll
        for (int s = 0; s < 2; s++) {
            const int kb = s * 8;
            uint32_t af[4][4], bf[4][2];
            #pragma unroll
            for (int mt = 0; mt < 4; mt++) {
                const int m = wm + mt * 16 + g;
                af[mt][0] = As[buf][kb + t4    ][m];
                af[mt][1] = As[buf][kb + t4    ][m + 8];
                af[mt][2] = As[buf][kb + t4 + 4][m];
                af[mt][3] = As[buf][kb + t4 + 4][m + 8];
            }
            #pragma unroll
            for (int nt = 0; nt < 4; nt++) {
                const int n = wn + nt * 8 + g;
                bf[nt][0] = Bs[buf][kb + t4    ][n];
                bf[nt][1] = Bs[buf][kb + t4 + 4][n];
            }
            #pragma unroll
            for (int mt = 0; mt < 4; mt++)
                #pragma unroll
                for (int nt = 0; nt < 4; nt++)
                    mma1688(acc[mt][nt], af[mt], bf[nt]);
        }
    };

    LOAD(0);
    STS(0);
    __syncthreads();

    for (int bk = 0; bk < CIN / BK; bk++) {
        const int buf = bk & 1;
        if (bk < CIN / BK - 1) LOAD(bk + 1);
        COMP(buf);
        if (bk < CIN / BK - 1) {
            __syncthreads();
            STS(buf ^ 1);
            __syncthreads();
        }
    }

    #pragma unroll
    for (int mt = 0; mt < 4; mt++) {
        const int row = mblk + wm + mt * 16 + g;
        #pragma unroll
        for (int nt = 0; nt < 4; nt++) {
            const int col = nblk + wn + nt * 8 + 2 * t4;
            float r0 = acc[mt][nt][0], r1 = acc[mt][nt][1];
            float r2 = acc[mt][nt][2], r3 = acc[mt][nt][3];
            if (MODE == 1) {
                r0 *= QSCALE; r1 *= QSCALE; r2 *= QSCALE; r3 *= QSCALE;
            } else if (MODE == 2) {
                r0 = 1.f / (1.f + __expf(-(r0 + bias[col])));
                r1 = 1.f / (1.f + __expf(-(r1 + bias[col + 1])));
                r2 = 1.f / (1.f + __expf(-(r2 + bias[col])));
                r3 = 1.f / (1.f + __expf(-(r3 + bias[col + 1])));
            } else if (MODE == 3) {
                r0 += bias[col]; r1 += bias[col + 1];
                r2 += bias[col]; r3 += bias[col + 1];
            }
            *(float2*)(C + (size_t)row * HID + col)       = make_float2(r0, r1);
            *(float2*)(C + (size_t)(row + 8) * HID + col) = make_float2(r2, r3);
        }
    }
}

// Batched projection: blockIdx.z selects {q, k, v, gate}
__global__ __launch_bounds__(256, 2)
void gemm_proj4(const float* __restrict__ q_x, const float* __restrict__ k_x,
                const float* __restrict__ v_x, const float* __restrict__ wt,
                const float* __restrict__ bg,
                float* __restrict__ oq, float* __restrict__ ok,
                float* __restrict__ ov, float* __restrict__ og)
{
    const int z    = blockIdx.z;
    const int mblk = blockIdx.x * BM;
    const int nblk = blockIdx.y * BN;
    switch (z) {
    case 0: gemm_core<1>(q_x, nullptr, wt + 0 * CIN * HID, nullptr, oq, mblk, nblk); break;
    case 1: gemm_core<0>(k_x, nullptr, wt + 1 * CIN * HID, nullptr, ok, mblk, nblk); break;
    case 2: gemm_core<0>(v_x, nullptr, wt + 2 * CIN * HID, nullptr, ov, mblk, nblk); break;
    default: gemm_core<2>(q_x, nullptr, wt + 3 * CIN * HID, bg,     og, mblk, nblk); break;
    }
}

__global__ __launch_bounds__(256, 2)
void gemm_out(const float* __restrict__ A, const float* __restrict__ A2,
              const float* __restrict__ Wt, const float* __restrict__ bias,
              float* __restrict__ C)
{
    gemm_core<3>(A, A2, Wt, bias, C, blockIdx.x * BM, blockIdx.y * BN);
}

// ---------------------------------------------------------------------------
// 256x256 transpose: dst[n][k] = src[k][n]
// ---------------------------------------------------------------------------
__global__ void transpose_w_kernel(const float* __restrict__ src, float* __restrict__ dst)
{
    __shared__ float tile[32][33];
    const int k0 = blockIdx.x * 32;
    const int n0 = blockIdx.y * 32;
    for (int j = threadIdx.y; j < 32; j += 8)
        tile[j][threadIdx.x] = src[(size_t)(k0 + j) * HID + n0 + threadIdx.x];
    __syncthreads();
    for (int j = threadIdx.y; j < 32; j += 8)
        dst[(size_t)(n0 + j) * CIN + k0 + threadIdx.x] = tile[threadIdx.x][j];
}

// ---------------------------------------------------------------------------
// Tensor-core attention. One CTA = 128 q-rows of one (n, h); 256 thr, 8 warps.
// K in 4 chunks of 128. Warp w owns q-rows w*16..w*16+15.
// Logits computed in log2 units (Q and biases pre-scaled by LOG2E) -> exp2f.
// ---------------------------------------------------------------------------
namespace {
constexpr int AW_Q  = 0;                 // Qs [32][136] u32 (tf32)
constexpr int AW_K  = AW_Q + 32 * 136;   // Ks [32][136]
constexpr int AW_V  = AW_K + 32 * 136;   // Vs [128][40]
constexpr int AW_P  = AW_V + 128 * 40;   // Ps [128][136]
constexpr int AW_BM = AW_P + 128 * 136;  // bms [512] (float)
constexpr int ATTN_SMEM_WORDS = AW_BM + 512;
constexpr int ATTN_SMEM = ATTN_SMEM_WORDS * 4;   // 126976 B
}

__global__ __launch_bounds__(256)
void attn_tc(const float* __restrict__ q, const float* __restrict__ kin,
             const float* __restrict__ vin, const float* __restrict__ bmask,
             const float* __restrict__ bp, float* __restrict__ o)
{
    extern __shared__ uint32_t su[];
    uint32_t* Qs = su + AW_Q;
    uint32_t* Ks = su + AW_K;
    uint32_t* Vs = su + AW_V;
    uint32_t* Ps = su + AW_P;
    float*    bms = (float*)(su + AW_BM);

    const int qt = blockIdx.x;   // 0..3
    const int h  = blockIdx.y;   // 0..7
    const int n  = blockIdx.z;   // 0..63
    const int tid  = threadIdx.x;
    const int lane = tid & 31;
    const int w    = tid >> 5;
    const int g    = lane >> 2;
    const int t4   = lane & 3;
    const int m0   = w * 16 + g;

    // ---- load Q tile (pre-scaled by LOG2E; QSCALE already applied upstream)
    {
        const int qrow = tid >> 1;
        const int c0   = (tid & 1) * 16;
        const float* src = q + ((size_t)n * QD + qt * 128 + qrow) * HID + h * CH + c0;
        #pragma unroll
        for (int i = 0; i < 16; i += 4) {
            float4 v = *(const float4*)(src + i);
            Qs[(c0 + i + 0) * LDP + qrow] = f2tf32(v.x * LOG2E);
            Qs[(c0 + i + 1) * LDP + qrow] = f2tf32(v.y * LOG2E);
            Qs[(c0 + i + 2) * LDP + qrow] = f2tf32(v.z * LOG2E);
            Qs[(c0 + i + 3) * LDP + qrow] = f2tf32(v.w * LOG2E);
        }
        for (int i = tid; i < KD; i += 256)
            bms[i] = bmask[(size_t)n * KD + i] * LOG2E;
    }
    __syncthreads();

    // ---- Q fragments (held in registers across all chunks)
    uint32_t qf[4][4];
    #pragma unroll
    for (int ks = 0; ks < 4; ks++) {
        qf[ks][0] = Qs[(ks * 8 + t4    ) * LDP + m0];
        qf[ks][1] = Qs[(ks * 8 + t4    ) * LDP + m0 + 8];
        qf[ks][2] = Qs[(ks * 8 + t4 + 4) * LDP + m0];
        qf[ks][3] = Qs[(ks * 8 + t4 + 4) * LDP + m0 + 8];
    }

    float mrow0 = -1e30f, mrow1 = -1e30f, lrow0 = 0.f, lrow1 = 0.f;
    float oacc[4][4];
    #pragma unroll
    for (int nt = 0; nt < 4; nt++)
        #pragma unroll
        for (int r = 0; r < 4; r++) oacc[nt][r] = 0.f;

    for (int kc = 0; kc < 4; kc++) {
        __syncthreads();   // previous chunk's consumers done with Ks/Vs
        // ---- stage K, V chunk (tf32)
        {
            const int kl   = tid & 127;
            const int half = (tid >> 7) * 16;
            const float* ksrc = kin + ((size_t)n * KD + kc * 128 + kl) * HID + h * CH + half;
            const float* vsrc = vin + ((size_t)n * KD + kc * 128 + kl) * HID + h * CH + half;
            #pragma unroll
            for (int i = 0; i < 16; i += 4) {
                float4 kv = *(const float4*)(ksrc + i);
                Ks[(half + i + 0) * LDP + kl] = f2tf32(kv.x);
                Ks[(half + i + 1) * LDP + kl] = f2tf32(kv.y);
                Ks[(half + i + 2) * LDP + kl] = f2tf32(kv.z);
                Ks[(half + i + 3) * LDP + kl] = f2tf32(kv.w);
                float4 vv = *(const float4*)(vsrc + i);
                Vs[kl * 40 + half + i + 0] = f2tf32(vv.x);
                Vs[kl * 40 + half + i + 1] = f2tf32(vv.y);
                Vs[kl * 40 + half + i + 2] = f2tf32(vv.z);
                Vs[kl * 40 + half + i + 3] = f2tf32(vv.w);
            }
        }
        __syncthreads();

        // ---- S = Q @ K^T  (16 q-rows x 128 keys per warp)
        float s[16][4];
        #pragma unroll
        for (int nt = 0; nt < 16; nt++) {
            s[nt][0] = s[nt][1] = s[nt][2] = s[nt][3] = 0.f;
            #pragma unroll
            for (int ks = 0; ks < 4; ks++) {
                uint32_t bf[2];
                bf[0] = Ks[(ks * 8 + t4    ) * LDP + nt * 8 + g];
                bf[1] = Ks[(ks * 8 + t4 + 4) * LDP + nt * 8 + g];
                mma1688(s[nt], qf[ks], bf);
            }
        }

        // ---- biases
        const float* bpr0 = bp + ((size_t)h * QD + qt * 128 + w * 16 + g) * KD + kc * 128;
        const float* bpr1 = bpr0 + 8 * KD;
        #pragma unroll
        for (int nt = 0; nt < 16; nt++) {
            const int c = nt * 8 + 2 * t4;
            const float2 b0 = *(const float2*)(bpr0 + c);
            const float2 b1 = *(const float2*)(bpr1 + c);
            const float bm0 = bms[kc * 128 + c];
            const float bm1 = bms[kc * 128 + c + 1];
            s[nt][0] = fmaf(b0.x, LOG2E, s[nt][0] + bm0);
            s[nt][1] = fmaf(b0.y, LOG2E, s[nt][1] + bm1);
            s[nt][2] = fmaf(b1.x, LOG2E, s[nt][2] + bm0);
            s[nt][3] = fmaf(b1.y, LOG2E, s[nt][3] + bm1);
        }

        // ---- row max (across 32 thread-local cols, then t4 quad)
        float mx0 = -1e30f, mx1 = -1e30f;
        #pragma unroll
        for (int nt = 0; nt < 16; nt++) {
            mx0 = fmaxf(mx0, fmaxf(s[nt][0], s[nt][1]));
            mx1 = fmaxf(mx1, fmaxf(s[nt][2], s[nt][3]));
        }
        mx0 = fmaxf(mx0, __shfl_xor_sync(0xffffffffu, mx0, 1));
        mx0 = fmaxf(mx0, __shfl_xor_sync(0xffffffffu, mx0, 2));
        mx1 = fmaxf(mx1, __shfl_xor_sync(0xffffffffu, mx1, 1));
        mx1 = fmaxf(mx1, __shfl_xor_sync(0xffffffffu, mx1, 2));

        const float mn0 = fmaxf(mrow0, mx0);
        const float mn1 = fmaxf(mrow1, mx1);
        const float cr0 = exp2f(mrow0 - mn0);
        const float cr1 = exp2f(mrow1 - mn1);
        mrow0 = mn0; mrow1 = mn1;
        lrow0 *= cr0; lrow1 *= cr1;
        #pragma unroll
        for (int nt = 0; nt < 4; nt++) {
            oacc[nt][0] *= cr0; oacc[nt][1] *= cr0;
            oacc[nt][2] *= cr1; oacc[nt][3] *= cr1;
        }

        // ---- P = exp2(s - m), store to smem (per-warp private columns)
        #pragma unroll
        for (int nt = 0; nt < 16; nt++) {
            const float p0 = exp2f(s[nt][0] - mrow0);
            const float p1 = exp2f(s[nt][1] - mrow0);
            const float p2 = exp2f(s[nt][2] - mrow1);
            const float p3 = exp2f(s[nt][3] - mrow1);
            lrow0 += p0 + p1;
            lrow1 += p2 + p3;
            const int c = nt * 8 + 2 * t4;
            Ps[(c + 0) * LDP + m0]     = f2tf32(p0);
            Ps[(c + 1) * LDP + m0]     = f2tf32(p1);
            Ps[(c + 0) * LDP + m0 + 8] = f2tf32(p2);
            Ps[(c + 1) * LDP + m0 + 8] = f2tf32(p3);
        }
        __syncwarp();

        // ---- O += P @ V
        #pragma unroll
        for (int ks = 0; ks < 16; ks++) {
            uint32_t pf[4];
            pf[0] = Ps[(ks * 8 + t4    ) * LDP + m0];
            pf[1] = Ps[(ks * 8 + t4    ) * LDP + m0 + 8];
            pf[2] = Ps[(ks * 8 + t4 + 4) * LDP + m0];
            pf[3] = Ps[(ks * 8 + t4 + 4) * LDP + m0 + 8];
            #pragma unroll
            for (int nt = 0; nt < 4; nt++) {
                uint32_t vf[2];
                vf[0] = Vs[(ks * 8 + t4    ) * 40 + nt * 8 + g];
                vf[1] = Vs[(ks * 8 + t4 + 4) * 40 + nt * 8 + g];
                mma1688(oacc[nt], pf, vf);
            }
        }
    }

    // ---- finalize: row sums across t4 quad, normalize, store
    lrow0 += __shfl_xor_sync(0xffffffffu, lrow0, 1);
    lrow0 += __shfl_xor_sync(0xffffffffu, lrow0, 2);
    lrow1 += __shfl_xor_sync(0xffffffffu, lrow1, 1);
    lrow1 += __shfl_xor_sync(0xffffffffu, lrow1, 2);
    const float inv0 = 1.f / lrow0;
    const float inv1 = 1.f / lrow1;

    float* ob0 = o + ((size_t)n * QD + qt * 128 + w * 16 + g) * HID + h * CH;
    float* ob1 = ob0 + 8 * HID;
    #pragma unroll
    for (int nt = 0; nt < 4; nt++) {
        const int c = nt * 8 + 2 * t4;
        *(float2*)(ob0 + c) = make_float2(oacc[nt][0] * inv0, oacc[nt][1] * inv0);
        *(float2*)(ob1 + c) = make_float2(oacc[nt][2] * inv1, oacc[nt][3] * inv1);
    }
}

// ---------------------------------------------------------------------------
extern "C" void kernel_launch(void* const* d_in, const int* in_sizes, int n_in,
                              void* d_out, int out_size)
{
    const float* q_x       = (const float*)d_in[0];
    const float* k_x       = (const float*)d_in[1];
    const float* v_x       = (const float*)d_in[2];
    const float* bias_mask = (const float*)d_in[3];
    const float* bias_pair = (const float*)d_in[4];
    const float* wq        = (const float*)d_in[5];
    const float* wk        = (const float*)d_in[6];
    const float* wv        = (const float*)d_in[7];
    const float* wg        = (const float*)d_in[8];
    const float* bg        = (const float*)d_in[9];
    const float* wo        = (const float*)d_in[10];
    const float* bo        = (const float*)d_in[11];
    float* out             = (float*)d_out;

    float *pq, *pk, *pv, *pg, *po, *pwt;
    cudaGetSymbolAddress((void**)&pq,  g_q);
    cudaGetSymbolAddress((void**)&pk,  g_k);
    cudaGetSymbolAddress((void**)&pv,  g_v);
    cudaGetSymbolAddress((void**)&pg,  g_g);
    cudaGetSymbolAddress((void**)&po,  g_o);
    cudaGetSymbolAddress((void**)&pwt, g_wt);

    static bool attr_set = false;
    if (!attr_set) {
        cudaFuncSetAttribute(attn_tc, cudaFuncAttributeMaxDynamicSharedMemorySize,
                             ATTN_SMEM);
        attr_set = true;
    }

    // weight transposes
    {
        dim3 gw(CIN / 32, HID / 32), bw(32, 8);
        transpose_w_kernel<<<gw, bw>>>(wq, pwt + 0 * CIN * HID);
        transpose_w_kernel<<<gw, bw>>>(wk, pwt + 1 * CIN * HID);
        transpose_w_kernel<<<gw, bw>>>(wv, pwt + 2 * CIN * HID);
        transpose_w_kernel<<<gw, bw>>>(wg, pwt + 3 * CIN * HID);
        transpose_w_kernel<<<gw, bw>>>(wo, pwt + 4 * CIN * HID);
    }

    // batched input projections (q, k, v, gate)
    {
        dim3 grid(MTOT / BM, HID / BN, 4), blk(256);
        gemm_proj4<<<grid, blk>>>(q_x, k_x, v_x, pwt, bg, pq, pk, pv, pg);
    }

    // tensor-core attention
    {
        dim3 grid(QD / 128, HEADS, NRES), blk(256);
        attn_tc<<<grid, blk, ATTN_SMEM>>>(pq, pk, pv, bias_mask, bias_pair, po);
    }

    // gated output projection -> d_out
    {
        dim3 grid(MTOT / BM, HID / BN), blk(256);
        gemm_out<<<grid, blk>>>(po, pg, pwt + 4 * CIN * HID, bo, out);
    }
}

// round 6
// speedup vs baseline: 2.4638x; 1.2192x over previous
#include <cuda_runtime.h>
#include <math.h>
#include <stdint.h>

// ---------------------------------------------------------------------------
// Problem constants
// ---------------------------------------------------------------------------
namespace {
constexpr int NRES  = 64;
constexpr int QD    = 512;
constexpr int KD    = 512;
constexpr int CIN   = 256;
constexpr int HEADS = 8;
constexpr int CH    = 32;
constexpr int HID   = 256;
constexpr int MTOT  = NRES * QD;                 // 32768
constexpr float QSCALE = 0.17677669529663687f;   // 1/sqrt(32)
constexpr float LOG2E  = 1.4426950408889634f;

// GEMM tiling
constexpr int BM = 128, BN = 128, BK = 16;
constexpr int LDP = 136;                         // 128 + 8 pad -> conflict-free frags
}

// Scratch (static device globals; no runtime allocation)
__device__ float g_q  [(size_t)MTOT * HID];
__device__ float g_k  [(size_t)MTOT * HID];
__device__ float g_v  [(size_t)MTOT * HID];
__device__ float g_g  [(size_t)MTOT * HID];
__device__ float g_o  [(size_t)MTOT * HID];

// ---------------------------------------------------------------------------
// helpers
// ---------------------------------------------------------------------------
__device__ __forceinline__ uint32_t f2tf32(float x) {
    uint32_t u;
    asm("cvt.rna.tf32.f32 %0, %1;" : "=r"(u) : "f"(x));
    return u;
}

// D += A * B  (m16n8k8, tf32 in, f32 accum)
__device__ __forceinline__ void mma1688(float* c, const uint32_t* a, const uint32_t* b) {
    asm volatile(
        "mma.sync.aligned.m16n8k8.row.col.f32.tf32.tf32.f32 "
        "{%0,%1,%2,%3}, {%4,%5,%6,%7}, {%8,%9}, {%0,%1,%2,%3};"
        : "+f"(c[0]), "+f"(c[1]), "+f"(c[2]), "+f"(c[3])
        : "r"(a[0]), "r"(a[1]), "r"(a[2]), "r"(a[3]), "r"(b[0]), "r"(b[1]));
}

// ---------------------------------------------------------------------------
// tf32 mma.sync GEMM core. W is [k][n] row-major (raw weight layout);
// B-transpose happens at the SMEM store. CTA tile 128x128x16, 8 warps.
// MODE 0: plain  1: *QSCALE  2: sigmoid(x+bias)  3: A=A.*A2, epi +bias
// ---------------------------------------------------------------------------
template <int MODE>
__device__ __forceinline__
void gemm_core(const float* __restrict__ A, const float* __restrict__ A2,
               const float* __restrict__ W, const float* __restrict__ bias,
               float* __restrict__ C, int mblk, int nblk)
{
    __shared__ uint32_t As[2][BK][LDP];
    __shared__ uint32_t Bs[2][BK][LDP];

    const int tid  = threadIdx.x;
    const int lane = tid & 31;
    const int w    = tid >> 5;
    const int g    = lane >> 2;
    const int t4   = lane & 3;
    const int wm   = (w >> 2) * 64;
    const int wn   = (w & 3) * 32;

    const int lm = tid >> 2;         // A: row 0..63 (x2)
    const int lk = (tid & 3) * 4;    // A: k offset
    const int bkr = tid >> 4;        // B: k row 0..15
    const int bnc = (tid & 15) * 8;  // B: n offset 0..120

    float acc[4][4][4];
    #pragma unroll
    for (int i = 0; i < 4; i++)
        #pragma unroll
        for (int j = 0; j < 4; j++)
            #pragma unroll
            for (int r = 0; r < 4; r++) acc[i][j][r] = 0.f;

    float4 va[2], ga[2], vb0, vb1;

    auto LOAD = [&](int bk) {
        const int k0 = bk * BK;
        #pragma unroll
        for (int r = 0; r < 2; r++) {
            const int m = lm + r * 64;
            va[r] = *(const float4*)(A  + (size_t)(mblk + m) * CIN + k0 + lk);
            if (MODE == 3)
                ga[r] = *(const float4*)(A2 + (size_t)(mblk + m) * CIN + k0 + lk);
        }
        vb0 = *(const float4*)(W + (size_t)(k0 + bkr) * HID + nblk + bnc);
        vb1 = *(const float4*)(W + (size_t)(k0 + bkr) * HID + nblk + bnc + 4);
    };
    auto STS = [&](int buf) {
        #pragma unroll
        for (int r = 0; r < 2; r++) {
            const int m = lm + r * 64;
            float4 v = va[r];
            if (MODE == 3) {
                v.x *= ga[r].x; v.y *= ga[r].y; v.z *= ga[r].z; v.w *= ga[r].w;
            }
            As[buf][lk + 0][m] = f2tf32(v.x);
            As[buf][lk + 1][m] = f2tf32(v.y);
            As[buf][lk + 2][m] = f2tf32(v.z);
            As[buf][lk + 3][m] = f2tf32(v.w);
        }
        Bs[buf][bkr][bnc + 0] = f2tf32(vb0.x);
        Bs[buf][bkr][bnc + 1] = f2tf32(vb0.y);
        Bs[buf][bkr][bnc + 2] = f2tf32(vb0.z);
        Bs[buf][bkr][bnc + 3] = f2tf32(vb0.w);
        Bs[buf][bkr][bnc + 4] = f2tf32(vb1.x);
        Bs[buf][bkr][bnc + 5] = f2tf32(vb1.y);
        Bs[buf][bkr][bnc + 6] = f2tf32(vb1.z);
        Bs[buf][bkr][bnc + 7] = f2tf32(vb1.w);
    };
    auto COMP = [&](int buf) {
        #pragma unroll
        for (int s = 0; s < 2; s++) {
            const int kb = s * 8;
            uint32_t af[4][4], bf[4][2];
            #pragma unroll
            for (int mt = 0; mt < 4; mt++) {
                const int m = wm + mt * 16 + g;
                af[mt][0] = As[buf][kb + t4    ][m];
                af[mt][1] = As[buf][kb + t4    ][m + 8];
                af[mt][2] = As[buf][kb + t4 + 4][m];
                af[mt][3] = As[buf][kb + t4 + 4][m + 8];
            }
            #pragma unroll
            for (int nt = 0; nt < 4; nt++) {
                const int n = wn + nt * 8 + g;
                bf[nt][0] = Bs[buf][kb + t4    ][n];
                bf[nt][1] = Bs[buf][kb + t4 + 4][n];
            }
            #pragma unroll
            for (int mt = 0; mt < 4; mt++)
                #pragma unroll
                for (int nt = 0; nt < 4; nt++)
                    mma1688(acc[mt][nt], af[mt], bf[nt]);
        }
    };

    LOAD(0);
    STS(0);
    __syncthreads();

    for (int bk = 0; bk < CIN / BK; bk++) {
        const int buf = bk & 1;
        if (bk < CIN / BK - 1) LOAD(bk + 1);
        COMP(buf);
        if (bk < CIN / BK - 1) {
            __syncthreads();
            STS(buf ^ 1);
            __syncthreads();
        }
    }

    #pragma unroll
    for (int mt = 0; mt < 4; mt++) {
        const int row = mblk + wm + mt * 16 + g;
        #pragma unroll
        for (int nt = 0; nt < 4; nt++) {
            const int col = nblk + wn + nt * 8 + 2 * t4;
            float r0 = acc[mt][nt][0], r1 = acc[mt][nt][1];
            float r2 = acc[mt][nt][2], r3 = acc[mt][nt][3];
            if (MODE == 1) {
                r0 *= QSCALE; r1 *= QSCALE; r2 *= QSCALE; r3 *= QSCALE;
            } else if (MODE == 2) {
                r0 = 1.f / (1.f + __expf(-(r0 + bias[col])));
                r1 = 1.f / (1.f + __expf(-(r1 + bias[col + 1])));
                r2 = 1.f / (1.f + __expf(-(r2 + bias[col])));
                r3 = 1.f / (1.f + __expf(-(r3 + bias[col + 1])));
            } else if (MODE == 3) {
                r0 += bias[col]; r1 += bias[col + 1];
                r2 += bias[col]; r3 += bias[col + 1];
            }
            *(float2*)(C + (size_t)row * HID + col)       = make_float2(r0, r1);
            *(float2*)(C + (size_t)(row + 8) * HID + col) = make_float2(r2, r3);
        }
    }
}

// Batched projection: blockIdx.z selects {q, k, v, gate}
__global__ __launch_bounds__(256, 2)
void gemm_proj4(const float* __restrict__ q_x, const float* __restrict__ k_x,
                const float* __restrict__ v_x,
                const float* __restrict__ wq, const float* __restrict__ wk,
                const float* __restrict__ wv, const float* __restrict__ wg,
                const float* __restrict__ bg,
                float* __restrict__ oq, float* __restrict__ ok,
                float* __restrict__ ov, float* __restrict__ og)
{
    const int z    = blockIdx.z;
    const int mblk = blockIdx.x * BM;
    const int nblk = blockIdx.y * BN;
    switch (z) {
    case 0: gemm_core<1>(q_x, nullptr, wq, nullptr, oq, mblk, nblk); break;
    case 1: gemm_core<0>(k_x, nullptr, wk, nullptr, ok, mblk, nblk); break;
    case 2: gemm_core<0>(v_x, nullptr, wv, nullptr, ov, mblk, nblk); break;
    default: gemm_core<2>(q_x, nullptr, wg, bg,     og, mblk, nblk); break;
    }
}

__global__ __launch_bounds__(256, 2)
void gemm_out(const float* __restrict__ A, const float* __restrict__ A2,
              const float* __restrict__ W, const float* __restrict__ bias,
              float* __restrict__ C)
{
    gemm_core<3>(A, A2, W, bias, C, blockIdx.x * BM, blockIdx.y * BN);
}

// ---------------------------------------------------------------------------
// Tensor-core attention. One CTA = 128 q-rows of one (n, h); 256 thr, 8 warps.
// K in 4 staged chunks of 128 keys, processed in halves of 64 (reg pressure).
// P never touches SMEM: S-fragment -> PV A-fragment via quad shfl (FA2-style).
// ---------------------------------------------------------------------------
namespace {
constexpr int AW_Q  = 0;                 // Qs [32][136] u32 (tf32)
constexpr int AW_K  = AW_Q + 32 * LDP;   // Ks [32][136]
constexpr int AW_V  = AW_K + 32 * LDP;   // Vs [128][40]
constexpr int AW_BM = AW_V + 128 * 40;   // bms [512] (float)
constexpr int ATTN_SMEM = (AW_BM + 512) * 4;   // 57344 B
}

__global__ __launch_bounds__(256, 2)
void attn_tc(const float* __restrict__ q, const float* __restrict__ kin,
             const float* __restrict__ vin, const float* __restrict__ bmask,
             const float* __restrict__ bp, float* __restrict__ o)
{
    extern __shared__ uint32_t su[];
    uint32_t* Qs = su + AW_Q;
    uint32_t* Ks = su + AW_K;
    uint32_t* Vs = su + AW_V;
    float*    bms = (float*)(su + AW_BM);

    const int qt = blockIdx.x;   // 0..3
    const int h  = blockIdx.y;   // 0..7
    const int n  = blockIdx.z;   // 0..63
    const int tid  = threadIdx.x;
    const int lane = tid & 31;
    const int w    = tid >> 5;
    const int g    = lane >> 2;
    const int t4   = lane & 3;
    const int m0   = w * 16 + g;

    // ---- load Q tile (pre-scaled by LOG2E; QSCALE applied upstream)
    {
        const int qrow = tid >> 1;
        const int c0   = (tid & 1) * 16;
        const float* src = q + ((size_t)n * QD + qt * 128 + qrow) * HID + h * CH + c0;
        #pragma unroll
        for (int i = 0; i < 16; i += 4) {
            float4 v = *(const float4*)(src + i);
            Qs[(c0 + i + 0) * LDP + qrow] = f2tf32(v.x * LOG2E);
            Qs[(c0 + i + 1) * LDP + qrow] = f2tf32(v.y * LOG2E);
            Qs[(c0 + i + 2) * LDP + qrow] = f2tf32(v.z * LOG2E);
            Qs[(c0 + i + 3) * LDP + qrow] = f2tf32(v.w * LOG2E);
        }
        for (int i = tid; i < KD; i += 256)
            bms[i] = bmask[(size_t)n * KD + i] * LOG2E;
    }
    __syncthreads();

    // ---- Q fragments (registers, all chunks)
    uint32_t qf[4][4];
    #pragma unroll
    for (int ks = 0; ks < 4; ks++) {
        qf[ks][0] = Qs[(ks * 8 + t4    ) * LDP + m0];
        qf[ks][1] = Qs[(ks * 8 + t4    ) * LDP + m0 + 8];
        qf[ks][2] = Qs[(ks * 8 + t4 + 4) * LDP + m0];
        qf[ks][3] = Qs[(ks * 8 + t4 + 4) * LDP + m0 + 8];
    }

    float mrow0 = -1e30f, mrow1 = -1e30f, lrow0 = 0.f, lrow1 = 0.f;
    float oacc[4][4];
    #pragma unroll
    for (int nt = 0; nt < 4; nt++)
        #pragma unroll
        for (int r = 0; r < 4; r++) oacc[nt][r] = 0.f;

    const int srcA = 4 * g + (t4 >> 1);
    const int srcB = srcA + 2;
    const bool podd = (t4 & 1);

    for (int kc = 0; kc < 4; kc++) {
        __syncthreads();   // prior consumers done with Ks/Vs
        // ---- stage K, V chunk (tf32)
        {
            const int kl   = tid & 127;
            const int half = (tid >> 7) * 16;
            const float* ksrc = kin + ((size_t)n * KD + kc * 128 + kl) * HID + h * CH + half;
            const float* vsrc = vin + ((size_t)n * KD + kc * 128 + kl) * HID + h * CH + half;
            #pragma unroll
            for (int i = 0; i < 16; i += 4) {
                float4 kv = *(const float4*)(ksrc + i);
                Ks[(half + i + 0) * LDP + kl] = f2tf32(kv.x);
                Ks[(half + i + 1) * LDP + kl] = f2tf32(kv.y);
                Ks[(half + i + 2) * LDP + kl] = f2tf32(kv.z);
                Ks[(half + i + 3) * LDP + kl] = f2tf32(kv.w);
                float4 vv = *(const float4*)(vsrc + i);
                Vs[kl * 40 + half + i + 0] = f2tf32(vv.x);
                Vs[kl * 40 + half + i + 1] = f2tf32(vv.y);
                Vs[kl * 40 + half + i + 2] = f2tf32(vv.z);
                Vs[kl * 40 + half + i + 3] = f2tf32(vv.w);
            }
        }
        __syncthreads();

        #pragma unroll
        for (int hf = 0; hf < 2; hf++) {
            const int kb = hf * 64;     // key offset within chunk

            // ---- S = Q @ K^T  (16 q-rows x 64 keys)
            float s[8][4];
            #pragma unroll
            for (int nt = 0; nt < 8; nt++) {
                s[nt][0] = s[nt][1] = s[nt][2] = s[nt][3] = 0.f;
                #pragma unroll
                for (int ks = 0; ks < 4; ks++) {
                    uint32_t bf[2];
                    bf[0] = Ks[(ks * 8 + t4    ) * LDP + kb + nt * 8 + g];
                    bf[1] = Ks[(ks * 8 + t4 + 4) * LDP + kb + nt * 8 + g];
                    mma1688(s[nt], qf[ks], bf);
                }
            }

            // ---- biases
            const float* bpr0 = bp + ((size_t)h * QD + qt * 128 + w * 16 + g) * KD
                              + kc * 128 + kb;
            const float* bpr1 = bpr0 + 8 * KD;
            #pragma unroll
            for (int nt = 0; nt < 8; nt++) {
                const int c = nt * 8 + 2 * t4;
                const float2 b0 = *(const float2*)(bpr0 + c);
                const float2 b1 = *(const float2*)(bpr1 + c);
                const float bm0 = bms[kc * 128 + kb + c];
                const float bm1 = bms[kc * 128 + kb + c + 1];
                s[nt][0] = fmaf(b0.x, LOG2E, s[nt][0] + bm0);
                s[nt][1] = fmaf(b0.y, LOG2E, s[nt][1] + bm1);
                s[nt][2] = fmaf(b1.x, LOG2E, s[nt][2] + bm0);
                s[nt][3] = fmaf(b1.y, LOG2E, s[nt][3] + bm1);
            }

            // ---- row max (local cols, then t4 quad)
            float mx0 = -1e30f, mx1 = -1e30f;
            #pragma unroll
            for (int nt = 0; nt < 8; nt++) {
                mx0 = fmaxf(mx0, fmaxf(s[nt][0], s[nt][1]));
                mx1 = fmaxf(mx1, fmaxf(s[nt][2], s[nt][3]));
            }
            mx0 = fmaxf(mx0, __shfl_xor_sync(0xffffffffu, mx0, 1));
            mx0 = fmaxf(mx0, __shfl_xor_sync(0xffffffffu, mx0, 2));
            mx1 = fmaxf(mx1, __shfl_xor_sync(0xffffffffu, mx1, 1));
            mx1 = fmaxf(mx1, __shfl_xor_sync(0xffffffffu, mx1, 2));

            const float mn0 = fmaxf(mrow0, mx0);
            const float mn1 = fmaxf(mrow1, mx1);
            const float cr0 = exp2f(mrow0 - mn0);
            const float cr1 = exp2f(mrow1 - mn1);
            mrow0 = mn0; mrow1 = mn1;
            lrow0 *= cr0; lrow1 *= cr1;
            #pragma unroll
            for (int nt = 0; nt < 4; nt++) {
                oacc[nt][0] *= cr0; oacc[nt][1] *= cr0;
                oacc[nt][2] *= cr1; oacc[nt][3] *= cr1;
            }

            // ---- P = exp2(s - m), accumulate row sums (in place)
            #pragma unroll
            for (int nt = 0; nt < 8; nt++) {
                s[nt][0] = exp2f(s[nt][0] - mrow0);
                s[nt][1] = exp2f(s[nt][1] - mrow0);
                s[nt][2] = exp2f(s[nt][2] - mrow1);
                s[nt][3] = exp2f(s[nt][3] - mrow1);
                lrow0 += s[nt][0] + s[nt][1];
                lrow1 += s[nt][2] + s[nt][3];
            }

            // ---- O += P @ V : A-fragment via quad shfl (no smem)
            #pragma unroll
            for (int ks = 0; ks < 8; ks++) {
                const float x0 = __shfl_sync(0xffffffffu, s[ks][0], srcA);
                const float x1 = __shfl_sync(0xffffffffu, s[ks][1], srcA);
                const float y0 = __shfl_sync(0xffffffffu, s[ks][2], srcA);
                const float y1 = __shfl_sync(0xffffffffu, s[ks][3], srcA);
                const float z0 = __shfl_sync(0xffffffffu, s[ks][0], srcB);
                const float z1 = __shfl_sync(0xffffffffu, s[ks][1], srcB);
                const float u0 = __shfl_sync(0xffffffffu, s[ks][2], srcB);
                const float u1 = __shfl_sync(0xffffffffu, s[ks][3], srcB);
                uint32_t pf[4];
                pf[0] = f2tf32(podd ? x1 : x0);
                pf[1] = f2tf32(podd ? y1 : y0);
                pf[2] = f2tf32(podd ? z1 : z0);
                pf[3] = f2tf32(podd ? u1 : u0);
                const int krow = kb + ks * 8;
                #pragma unroll
                for (int nt = 0; nt < 4; nt++) {
                    uint32_t vf[2];
                    vf[0] = Vs[(krow + t4    ) * 40 + nt * 8 + g];
                    vf[1] = Vs[(krow + t4 + 4) * 40 + nt * 8 + g];
                    mma1688(oacc[nt], pf, vf);
                }
            }
        }
    }

    // ---- finalize
    lrow0 += __shfl_xor_sync(0xffffffffu, lrow0, 1);
    lrow0 += __shfl_xor_sync(0xffffffffu, lrow0, 2);
    lrow1 += __shfl_xor_sync(0xffffffffu, lrow1, 1);
    lrow1 += __shfl_xor_sync(0xffffffffu, lrow1, 2);
    const float inv0 = 1.f / lrow0;
    const float inv1 = 1.f / lrow1;

    float* ob0 = o + ((size_t)n * QD + qt * 128 + w * 16 + g) * HID + h * CH;
    float* ob1 = ob0 + 8 * HID;
    #pragma unroll
    for (int nt = 0; nt < 4; nt++) {
        const int c = nt * 8 + 2 * t4;
        *(float2*)(ob0 + c) = make_float2(oacc[nt][0] * inv0, oacc[nt][1] * inv0);
        *(float2*)(ob1 + c) = make_float2(oacc[nt][2] * inv1, oacc[nt][3] * inv1);
    }
}

// ---------------------------------------------------------------------------
extern "C" void kernel_launch(void* const* d_in, const int* in_sizes, int n_in,
                              void* d_out, int out_size)
{
    const float* q_x       = (const float*)d_in[0];
    const float* k_x       = (const float*)d_in[1];
    const float* v_x       = (const float*)d_in[2];
    const float* bias_mask = (const float*)d_in[3];
    const float* bias_pair = (const float*)d_in[4];
    const float* wq        = (const float*)d_in[5];
    const float* wk        = (const float*)d_in[6];
    const float* wv        = (const float*)d_in[7];
    const float* wg        = (const float*)d_in[8];
    const float* bg        = (const float*)d_in[9];
    const float* wo        = (const float*)d_in[10];
    const float* bo        = (const float*)d_in[11];
    float* out             = (float*)d_out;

    float *pq, *pk, *pv, *pg, *po;
    cudaGetSymbolAddress((void**)&pq, g_q);
    cudaGetSymbolAddress((void**)&pk, g_k);
    cudaGetSymbolAddress((void**)&pv, g_v);
    cudaGetSymbolAddress((void**)&pg, g_g);
    cudaGetSymbolAddress((void**)&po, g_o);

    static bool attr_set = false;
    if (!attr_set) {
        cudaFuncSetAttribute(attn_tc, cudaFuncAttributeMaxDynamicSharedMemorySize,
                             ATTN_SMEM);
        attr_set = true;
    }

    // batched input projections (q, k, v, gate) — weights consumed in raw [k][n]
    {
        dim3 grid(MTOT / BM, HID / BN, 4), blk(256);
        gemm_proj4<<<grid, blk>>>(q_x, k_x, v_x, wq, wk, wv, wg, bg,
                                  pq, pk, pv, pg);
    }

    // tensor-core attention
    {
        dim3 grid(QD / 128, HEADS, NRES), blk(256);
        attn_tc<<<grid, blk, ATTN_SMEM>>>(pq, pk, pv, bias_mask, bias_pair, po);
    }

    // gated output projection -> d_out
    {
        dim3 grid(MTOT / BM, HID / BN), blk(256);
        gemm_out<<<grid, blk>>>(po, pg, wo, bo, out);
    }
}

// round 7
// speedup vs baseline: 2.5745x; 1.0449x over previous
#include <cuda_runtime.h>
#include <math.h>
#include <stdint.h>

// ---------------------------------------------------------------------------
// Problem constants
// ---------------------------------------------------------------------------
namespace {
constexpr int NRES  = 64;
constexpr int QD    = 512;
constexpr int KD    = 512;
constexpr int CIN   = 256;
constexpr int HEADS = 8;
constexpr int CH    = 32;
constexpr int HID   = 256;
constexpr int MTOT  = NRES * QD;                 // 32768
constexpr float QSCALE = 0.17677669529663687f;   // 1/sqrt(32)
constexpr float LOG2E  = 1.4426950408889634f;

// GEMM tiling
constexpr int BM = 128, BN = 128, BK = 16;
constexpr int LDP = 136;                         // 128 + 8 pad -> conflict-free frags
}

// Scratch (static device globals; no runtime allocation)
__device__ float g_q  [(size_t)MTOT * HID];
__device__ float g_k  [(size_t)MTOT * HID];
__device__ float g_v  [(size_t)MTOT * HID];
__device__ float g_g  [(size_t)MTOT * HID];
__device__ float g_o  [(size_t)MTOT * HID];

// ---------------------------------------------------------------------------
// helpers
// ---------------------------------------------------------------------------
__device__ __forceinline__ uint32_t f2tf32(float x) {
    uint32_t u;
    asm("cvt.rna.tf32.f32 %0, %1;" : "=r"(u) : "f"(x));
    return u;
}

// D += A * B  (m16n8k8, tf32 in, f32 accum)
__device__ __forceinline__ void mma1688(float* c, const uint32_t* a, const uint32_t* b) {
    asm volatile(
        "mma.sync.aligned.m16n8k8.row.col.f32.tf32.tf32.f32 "
        "{%0,%1,%2,%3}, {%4,%5,%6,%7}, {%8,%9}, {%0,%1,%2,%3};"
        : "+f"(c[0]), "+f"(c[1]), "+f"(c[2]), "+f"(c[3])
        : "r"(a[0]), "r"(a[1]), "r"(a[2]), "r"(a[3]), "r"(b[0]), "r"(b[1]));
}

// ---------------------------------------------------------------------------
// tf32 mma.sync GEMM core. W is [k][n] row-major (raw weight layout);
// B-transpose happens at the SMEM store. CTA tile 128x128x16, 8 warps.
// Single barrier per k-iteration (COMP(buf) and STS(buf^1) touch disjoint
// buffers; the end-of-iter barrier covers the cross-iteration hazard).
// MODE 0: plain  1: *QSCALE  2: sigmoid(x+bias)  3: A=A.*A2, epi +bias
// ---------------------------------------------------------------------------
template <int MODE>
__device__ __forceinline__
void gemm_core(const float* __restrict__ A, const float* __restrict__ A2,
               const float* __restrict__ W, const float* __restrict__ bias,
               float* __restrict__ C, int mblk, int nblk)
{
    __shared__ uint32_t As[2][BK][LDP];
    __shared__ uint32_t Bs[2][BK][LDP];

    const int tid  = threadIdx.x;
    const int lane = tid & 31;
    const int w    = tid >> 5;
    const int g    = lane >> 2;
    const int t4   = lane & 3;
    const int wm   = (w >> 2) * 64;
    const int wn   = (w & 3) * 32;

    const int lm = tid >> 2;         // A: row 0..63 (x2)
    const int lk = (tid & 3) * 4;    // A: k offset
    const int bkr = tid >> 4;        // B: k row 0..15
    const int bnc = (tid & 15) * 8;  // B: n offset 0..120

    float acc[4][4][4];
    #pragma unroll
    for (int i = 0; i < 4; i++)
        #pragma unroll
        for (int j = 0; j < 4; j++)
            #pragma unroll
            for (int r = 0; r < 4; r++) acc[i][j][r] = 0.f;

    float4 va[2], ga[2], vb0, vb1;

    auto LOAD = [&](int bk) {
        const int k0 = bk * BK;
        #pragma unroll
        for (int r = 0; r < 2; r++) {
            const int m = lm + r * 64;
            va[r] = *(const float4*)(A  + (size_t)(mblk + m) * CIN + k0 + lk);
            if (MODE == 3)
                ga[r] = *(const float4*)(A2 + (size_t)(mblk + m) * CIN + k0 + lk);
        }
        vb0 = *(const float4*)(W + (size_t)(k0 + bkr) * HID + nblk + bnc);
        vb1 = *(const float4*)(W + (size_t)(k0 + bkr) * HID + nblk + bnc + 4);
    };
    auto STS = [&](int buf) {
        #pragma unroll
        for (int r = 0; r < 2; r++) {
            const int m = lm + r * 64;
            float4 v = va[r];
            if (MODE == 3) {
                v.x *= ga[r].x; v.y *= ga[r].y; v.z *= ga[r].z; v.w *= ga[r].w;
            }
            As[buf][lk + 0][m] = f2tf32(v.x);
            As[buf][lk + 1][m] = f2tf32(v.y);
            As[buf][lk + 2][m] = f2tf32(v.z);
            As[buf][lk + 3][m] = f2tf32(v.w);
        }
        Bs[buf][bkr][bnc + 0] = f2tf32(vb0.x);
        Bs[buf][bkr][bnc + 1] = f2tf32(vb0.y);
        Bs[buf][bkr][bnc + 2] = f2tf32(vb0.z);
        Bs[buf][bkr][bnc + 3] = f2tf32(vb0.w);
        Bs[buf][bkr][bnc + 4] = f2tf32(vb1.x);
        Bs[buf][bkr][bnc + 5] = f2tf32(vb1.y);
        Bs[buf][bkr][bnc + 6] = f2tf32(vb1.z);
        Bs[buf][bkr][bnc + 7] = f2tf32(vb1.w);
    };
    auto COMP = [&](int buf) {
        #pragma unroll
        for (int s = 0; s < 2; s++) {
            const int kb = s * 8;
            uint32_t af[4][4], bf[4][2];
            #pragma unroll
            for (int mt = 0; mt < 4; mt++) {
                const int m = wm + mt * 16 + g;
                af[mt][0] = As[buf][kb + t4    ][m];
                af[mt][1] = As[buf][kb + t4    ][m + 8];
                af[mt][2] = As[buf][kb + t4 + 4][m];
                af[mt][3] = As[buf][kb + t4 + 4][m + 8];
            }
            #pragma unroll
            for (int nt = 0; nt < 4; nt++) {
                const int n = wn + nt * 8 + g;
                bf[nt][0] = Bs[buf][kb + t4    ][n];
                bf[nt][1] = Bs[buf][kb + t4 + 4][n];
            }
            #pragma unroll
            for (int mt = 0; mt < 4; mt++)
                #pragma unroll
                for (int nt = 0; nt < 4; nt++)
                    mma1688(acc[mt][nt], af[mt], bf[nt]);
        }
    };

    LOAD(0);
    STS(0);
    __syncthreads();

    for (int bk = 0; bk < CIN / BK; bk++) {
        const int buf = bk & 1;
        if (bk < CIN / BK - 1) LOAD(bk + 1);   // gmem prefetch (latency under COMP)
        COMP(buf);
        if (bk < CIN / BK - 1) STS(buf ^ 1);   // disjoint buffer from COMP(buf)
        __syncthreads();                       // single barrier per iteration
    }

    #pragma unroll
    for (int mt = 0; mt < 4; mt++) {
        const int row = mblk + wm + mt * 16 + g;
        #pragma unroll
        for (int nt = 0; nt < 4; nt++) {
            const int col = nblk + wn + nt * 8 + 2 * t4;
            float r0 = acc[mt][nt][0], r1 = acc[mt][nt][1];
            float r2 = acc[mt][nt][2], r3 = acc[mt][nt][3];
            if (MODE == 1) {
                r0 *= QSCALE; r1 *= QSCALE; r2 *= QSCALE; r3 *= QSCALE;
            } else if (MODE == 2) {
                r0 = 1.f / (1.f + __expf(-(r0 + bias[col])));
                r1 = 1.f / (1.f + __expf(-(r1 + bias[col + 1])));
                r2 = 1.f / (1.f + __expf(-(r2 + bias[col])));
                r3 = 1.f / (1.f + __expf(-(r3 + bias[col + 1])));
            } else if (MODE == 3) {
                r0 += bias[col]; r1 += bias[col + 1];
                r2 += bias[col]; r3 += bias[col + 1];
            }
            *(float2*)(C + (size_t)row * HID + col)       = make_float2(r0, r1);
            *(float2*)(C + (size_t)(row + 8) * HID + col) = make_float2(r2, r3);
        }
    }
}

// Batched projection: blockIdx.z selects {q, k, v, gate}
__global__ __launch_bounds__(256, 2)
void gemm_proj4(const float* __restrict__ q_x, const float* __restrict__ k_x,
                const float* __restrict__ v_x,
                const float* __restrict__ wq, const float* __restrict__ wk,
                const float* __restrict__ wv, const float* __restrict__ wg,
                const float* __restrict__ bg,
                float* __restrict__ oq, float* __restrict__ ok,
                float* __restrict__ ov, float* __restrict__ og)
{
    const int z    = blockIdx.z;
    const int mblk = blockIdx.x * BM;
    const int nblk = blockIdx.y * BN;
    switch (z) {
    case 0: gemm_core<1>(q_x, nullptr, wq, nullptr, oq, mblk, nblk); break;
    case 1: gemm_core<0>(k_x, nullptr, wk, nullptr, ok, mblk, nblk); break;
    case 2: gemm_core<0>(v_x, nullptr, wv, nullptr, ov, mblk, nblk); break;
    default: gemm_core<2>(q_x, nullptr, wg, bg,     og, mblk, nblk); break;
    }
}

__global__ __launch_bounds__(256, 2)
void gemm_out(const float* __restrict__ A, const float* __restrict__ A2,
              const float* __restrict__ W, const float* __restrict__ bias,
              float* __restrict__ C)
{
    gemm_core<3>(A, A2, W, bias, C, blockIdx.x * BM, blockIdx.y * BN);
}

// ---------------------------------------------------------------------------
// Tensor-core attention. One CTA = 128 q-rows of one (n, h); 256 thr, 8 warps.
// K staged in 4 chunks of 128 keys; softmax processed in 32-key passes to
// cap register pressure (targets 3 CTAs/SM). Q-fragments reloaded from SMEM
// per pass so their liveness stays inside the S-phase.
// ---------------------------------------------------------------------------
namespace {
constexpr int AW_Q  = 0;                 // Qs [32][136] u32 (tf32)
constexpr int AW_K  = AW_Q + 32 * LDP;   // Ks [32][136]
constexpr int AW_V  = AW_K + 32 * LDP;   // Vs [128][40]
constexpr int AW_BM = AW_V + 128 * 40;   // bms [512] (float)
constexpr int ATTN_SMEM = (AW_BM + 512) * 4;   // 57344 B
}

__global__ __launch_bounds__(256, 3)
void attn_tc(const float* __restrict__ q, const float* __restrict__ kin,
             const float* __restrict__ vin, const float* __restrict__ bmask,
             const float* __restrict__ bp, float* __restrict__ o)
{
    extern __shared__ uint32_t su[];
    uint32_t* Qs = su + AW_Q;
    uint32_t* Ks = su + AW_K;
    uint32_t* Vs = su + AW_V;
    float*    bms = (float*)(su + AW_BM);

    const int qt = blockIdx.x;   // 0..3
    const int h  = blockIdx.y;   // 0..7
    const int n  = blockIdx.z;   // 0..63
    const int tid  = threadIdx.x;
    const int lane = tid & 31;
    const int w    = tid >> 5;
    const int g    = lane >> 2;
    const int t4   = lane & 3;
    const int m0   = w * 16 + g;

    // ---- load Q tile (pre-scaled by LOG2E; QSCALE applied upstream)
    {
        const int qrow = tid >> 1;
        const int c0   = (tid & 1) * 16;
        const float* src = q + ((size_t)n * QD + qt * 128 + qrow) * HID + h * CH + c0;
        #pragma unroll
        for (int i = 0; i < 16; i += 4) {
            float4 v = *(const float4*)(src + i);
            Qs[(c0 + i + 0) * LDP + qrow] = f2tf32(v.x * LOG2E);
            Qs[(c0 + i + 1) * LDP + qrow] = f2tf32(v.y * LOG2E);
            Qs[(c0 + i + 2) * LDP + qrow] = f2tf32(v.z * LOG2E);
            Qs[(c0 + i + 3) * LDP + qrow] = f2tf32(v.w * LOG2E);
        }
        for (int i = tid; i < KD; i += 256)
            bms[i] = bmask[(size_t)n * KD + i] * LOG2E;
    }

    float mrow0 = -1e30f, mrow1 = -1e30f, lrow0 = 0.f, lrow1 = 0.f;
    float oacc[4][4];
    #pragma unroll
    for (int nt = 0; nt < 4; nt++)
        #pragma unroll
        for (int r = 0; r < 4; r++) oacc[nt][r] = 0.f;

    const int srcA = 4 * g + (t4 >> 1);
    const int srcB = srcA + 2;
    const bool podd = (t4 & 1);

    for (int kc = 0; kc < 4; kc++) {
        __syncthreads();   // prior consumers done with Ks/Vs (also covers Q/bms init)
        // ---- stage K, V chunk (tf32)
        {
            const int kl   = tid & 127;
            const int half = (tid >> 7) * 16;
            const float* ksrc = kin + ((size_t)n * KD + kc * 128 + kl) * HID + h * CH + half;
            const float* vsrc = vin + ((size_t)n * KD + kc * 128 + kl) * HID + h * CH + half;
            #pragma unroll
            for (int i = 0; i < 16; i += 4) {
                float4 kv = *(const float4*)(ksrc + i);
                Ks[(half + i + 0) * LDP + kl] = f2tf32(kv.x);
                Ks[(half + i + 1) * LDP + kl] = f2tf32(kv.y);
                Ks[(half + i + 2) * LDP + kl] = f2tf32(kv.z);
                Ks[(half + i + 3) * LDP + kl] = f2tf32(kv.w);
                float4 vv = *(const float4*)(vsrc + i);
                Vs[kl * 40 + half + i + 0] = f2tf32(vv.x);
                Vs[kl * 40 + half + i + 1] = f2tf32(vv.y);
                Vs[kl * 40 + half + i + 2] = f2tf32(vv.z);
                Vs[kl * 40 + half + i + 3] = f2tf32(vv.w);
            }
        }
        __syncthreads();

        #pragma unroll
        for (int qtr = 0; qtr < 4; qtr++) {
            const int kb = qtr * 32;     // key offset within chunk

            // ---- Q fragments (reloaded per pass; live only in S-phase)
            uint32_t qf[4][4];
            #pragma unroll
            for (int ks = 0; ks < 4; ks++) {
                qf[ks][0] = Qs[(ks * 8 + t4    ) * LDP + m0];
                qf[ks][1] = Qs[(ks * 8 + t4    ) * LDP + m0 + 8];
                qf[ks][2] = Qs[(ks * 8 + t4 + 4) * LDP + m0];
                qf[ks][3] = Qs[(ks * 8 + t4 + 4) * LDP + m0 + 8];
            }

            // ---- S = Q @ K^T  (16 q-rows x 32 keys)
            float s[4][4];
            #pragma unroll
            for (int nt = 0; nt < 4; nt++) {
                s[nt][0] = s[nt][1] = s[nt][2] = s[nt][3] = 0.f;
                #pragma unroll
                for (int ks = 0; ks < 4; ks++) {
                    uint32_t bf[2];
                    bf[0] = Ks[(ks * 8 + t4    ) * LDP + kb + nt * 8 + g];
                    bf[1] = Ks[(ks * 8 + t4 + 4) * LDP + kb + nt * 8 + g];
                    mma1688(s[nt], qf[ks], bf);
                }
            }

            // ---- biases
            const float* bpr0 = bp + ((size_t)h * QD + qt * 128 + w * 16 + g) * KD
                              + kc * 128 + kb;
            const float* bpr1 = bpr0 + 8 * KD;
            #pragma unroll
            for (int nt = 0; nt < 4; nt++) {
                const int c = nt * 8 + 2 * t4;
                const float2 b0 = *(const float2*)(bpr0 + c);
                const float2 b1 = *(const float2*)(bpr1 + c);
                const float bm0 = bms[kc * 128 + kb + c];
                const float bm1 = bms[kc * 128 + kb + c + 1];
                s[nt][0] = fmaf(b0.x, LOG2E, s[nt][0] + bm0);
                s[nt][1] = fmaf(b0.y, LOG2E, s[nt][1] + bm1);
                s[nt][2] = fmaf(b1.x, LOG2E, s[nt][2] + bm0);
                s[nt][3] = fmaf(b1.y, LOG2E, s[nt][3] + bm1);
            }

            // ---- row max (local cols, then t4 quad)
            float mx0 = -1e30f, mx1 = -1e30f;
            #pragma unroll
            for (int nt = 0; nt < 4; nt++) {
                mx0 = fmaxf(mx0, fmaxf(s[nt][0], s[nt][1]));
                mx1 = fmaxf(mx1, fmaxf(s[nt][2], s[nt][3]));
            }
            mx0 = fmaxf(mx0, __shfl_xor_sync(0xffffffffu, mx0, 1));
            mx0 = fmaxf(mx0, __shfl_xor_sync(0xffffffffu, mx0, 2));
            mx1 = fmaxf(mx1, __shfl_xor_sync(0xffffffffu, mx1, 1));
            mx1 = fmaxf(mx1, __shfl_xor_sync(0xffffffffu, mx1, 2));

            const float mn0 = fmaxf(mrow0, mx0);
            const float mn1 = fmaxf(mrow1, mx1);
            const float cr0 = exp2f(mrow0 - mn0);
            const float cr1 = exp2f(mrow1 - mn1);
            mrow0 = mn0; mrow1 = mn1;
            lrow0 *= cr0; lrow1 *= cr1;
            #pragma unroll
            for (int nt = 0; nt < 4; nt++) {
                oacc[nt][0] *= cr0; oacc[nt][1] *= cr0;
                oacc[nt][2] *= cr1; oacc[nt][3] *= cr1;
            }

            // ---- P = exp2(s - m), accumulate row sums (in place)
            #pragma unroll
            for (int nt = 0; nt < 4; nt++) {
                s[nt][0] = exp2f(s[nt][0] - mrow0);
                s[nt][1] = exp2f(s[nt][1] - mrow0);
                s[nt][2] = exp2f(s[nt][2] - mrow1);
                s[nt][3] = exp2f(s[nt][3] - mrow1);
                lrow0 += s[nt][0] + s[nt][1];
                lrow1 += s[nt][2] + s[nt][3];
            }

            // ---- O += P @ V : A-fragment via quad shfl (no smem)
            #pragma unroll
            for (int ks = 0; ks < 4; ks++) {
                const float x0 = __shfl_sync(0xffffffffu, s[ks][0], srcA);
                const float x1 = __shfl_sync(0xffffffffu, s[ks][1], srcA);
                const float y0 = __shfl_sync(0xffffffffu, s[ks][2], srcA);
                const float y1 = __shfl_sync(0xffffffffu, s[ks][3], srcA);
                const float z0 = __shfl_sync(0xffffffffu, s[ks][0], srcB);
                const float z1 = __shfl_sync(0xffffffffu, s[ks][1], srcB);
                const float u0 = __shfl_sync(0xffffffffu, s[ks][2], srcB);
                const float u1 = __shfl_sync(0xffffffffu, s[ks][3], srcB);
                uint32_t pf[4];
                pf[0] = f2tf32(podd ? x1 : x0);
                pf[1] = f2tf32(podd ? y1 : y0);
                pf[2] = f2tf32(podd ? z1 : z0);
                pf[3] = f2tf32(podd ? u1 : u0);
                const int krow = kb + ks * 8;
                #pragma unroll
                for (int nt = 0; nt < 4; nt++) {
                    uint32_t vf[2];
                    vf[0] = Vs[(krow + t4    ) * 40 + nt * 8 + g];
                    vf[1] = Vs[(krow + t4 + 4) * 40 + nt * 8 + g];
                    mma1688(oacc[nt], pf, vf);
                }
            }
        }
    }

    // ---- finalize
    lrow0 += __shfl_xor_sync(0xffffffffu, lrow0, 1);
    lrow0 += __shfl_xor_sync(0xffffffffu, lrow0, 2);
    lrow1 += __shfl_xor_sync(0xffffffffu, lrow1, 1);
    lrow1 += __shfl_xor_sync(0xffffffffu, lrow1, 2);
    const float inv0 = 1.f / lrow0;
    const float inv1 = 1.f / lrow1;

    float* ob0 = o + ((size_t)n * QD + qt * 128 + w * 16 + g) * HID + h * CH;
    float* ob1 = ob0 + 8 * HID;
    #pragma unroll
    for (int nt = 0; nt < 4; nt++) {
        const int c = nt * 8 + 2 * t4;
        *(float2*)(ob0 + c) = make_float2(oacc[nt][0] * inv0, oacc[nt][1] * inv0);
        *(float2*)(ob1 + c) = make_float2(oacc[nt][2] * inv1, oacc[nt][3] * inv1);
    }
}

// ---------------------------------------------------------------------------
extern "C" void kernel_launch(void* const* d_in, const int* in_sizes, int n_in,
                              void* d_out, int out_size)
{
    const float* q_x       = (const float*)d_in[0];
    const float* k_x       = (const float*)d_in[1];
    const float* v_x       = (const float*)d_in[2];
    const float* bias_mask = (const float*)d_in[3];
    const float* bias_pair = (const float*)d_in[4];
    const float* wq        = (const float*)d_in[5];
    const float* wk        = (const float*)d_in[6];
    const float* wv        = (const float*)d_in[7];
    const float* wg        = (const float*)d_in[8];
    const float* bg        = (const float*)d_in[9];
    const float* wo        = (const float*)d_in[10];
    const float* bo        = (const float*)d_in[11];
    float* out             = (float*)d_out;

    float *pq, *pk, *pv, *pg, *po;
    cudaGetSymbolAddress((void**)&pq, g_q);
    cudaGetSymbolAddress((void**)&pk, g_k);
    cudaGetSymbolAddress((void**)&pv, g_v);
    cudaGetSymbolAddress((void**)&pg, g_g);
    cudaGetSymbolAddress((void**)&po, g_o);

    static bool attr_set = false;
    if (!attr_set) {
        cudaFuncSetAttribute(attn_tc, cudaFuncAttributeMaxDynamicSharedMemorySize,
                             ATTN_SMEM);
        attr_set = true;
    }

    // batched input projections (q, k, v, gate) — weights consumed in raw [k][n]
    {
        dim3 grid(MTOT / BM, HID / BN, 4), blk(256);
        gemm_proj4<<<grid, blk>>>(q_x, k_x, v_x, wq, wk, wv, wg, bg,
                                  pq, pk, pv, pg);
    }

    // tensor-core attention
    {
        dim3 grid(QD / 128, HEADS, NRES), blk(256);
        attn_tc<<<grid, blk, ATTN_SMEM>>>(pq, pk, pv, bias_mask, bias_pair, po);
    }

    // gated output projection -> d_out
    {
        dim3 grid(MTOT / BM, HID / BN), blk(256);
        gemm_out<<<grid, blk>>>(po, pg, wo, bo, out);
    }
}

// round 8
// speedup vs baseline: 2.8954x; 1.1247x over previous
#include <cuda_runtime.h>
#include <math.h>
#include <stdint.h>

// ---------------------------------------------------------------------------
// Problem constants
// ---------------------------------------------------------------------------
namespace {
constexpr int NRES  = 64;
constexpr int QD    = 512;
constexpr int KD    = 512;
constexpr int CIN   = 256;
constexpr int HEADS = 8;
constexpr int CH    = 32;
constexpr int HID   = 256;
constexpr int MTOT  = NRES * QD;                 // 32768
constexpr float QSCALE = 0.17677669529663687f;   // 1/sqrt(32)
constexpr float LOG2E  = 1.4426950408889634f;

// GEMM tiling
constexpr int BM = 128, BN = 128, BK = 16;
constexpr int LDP = 136;                         // attn smem pad (u32 words)

// GEMM smem layout (fp32, cp.async staged)
constexpr int LDA    = 20;                       // A row stride (floats), conflict-free
constexpr int LDB    = 136;                      // B row stride (floats), conflict-free
constexpr int STAGES = 3;
constexpr int A_STG  = BM * LDA;                 // 2560 floats
constexpr int B_STG  = BK * LDB;                 // 2176 floats
constexpr int GEMM_SMEM = STAGES * (A_STG + B_STG) * 4;  // 56832 B
}

// Scratch (static device globals; no runtime allocation)
__device__ float g_q  [(size_t)MTOT * HID];
__device__ float g_k  [(size_t)MTOT * HID];
__device__ float g_v  [(size_t)MTOT * HID];
__device__ float g_g  [(size_t)MTOT * HID];
__device__ float g_o  [(size_t)MTOT * HID];

// ---------------------------------------------------------------------------
// helpers
// ---------------------------------------------------------------------------
__device__ __forceinline__ uint32_t f2tf32(float x) {
    uint32_t u;
    asm("cvt.rna.tf32.f32 %0, %1;" : "=r"(u) : "f"(x));
    return u;
}

// D += A * B  (m16n8k8, tf32 in, f32 accum)
__device__ __forceinline__ void mma1688(float* c, const uint32_t* a, const uint32_t* b) {
    asm volatile(
        "mma.sync.aligned.m16n8k8.row.col.f32.tf32.tf32.f32 "
        "{%0,%1,%2,%3}, {%4,%5,%6,%7}, {%8,%9}, {%0,%1,%2,%3};"
        : "+f"(c[0]), "+f"(c[1]), "+f"(c[2]), "+f"(c[3])
        : "r"(a[0]), "r"(a[1]), "r"(a[2]), "r"(a[3]), "r"(b[0]), "r"(b[1]));
}

__device__ __forceinline__ void cp_async16(uint32_t smem_addr, const void* gptr) {
    asm volatile("cp.async.ca.shared.global [%0], [%1], 16;"
                 :: "r"(smem_addr), "l"(gptr));
}
#define CP_COMMIT() asm volatile("cp.async.commit_group;" ::: "memory")
#define CP_WAIT(n)  asm volatile("cp.async.wait_group %0;" :: "n"(n) : "memory")

// ---------------------------------------------------------------------------
// tf32 mma.sync GEMM core, cp.async 3-stage pipeline.
// A [m][k] raw fp32 in gmem; W [k][n] raw fp32. Conversion to tf32 (rna)
// happens at fragment-load time. CTA tile 128x128x16, 8 warps (2x4).
// MODE 0: plain  1: *QSCALE  2: sigmoid(x+bias)  3: +bias
// ---------------------------------------------------------------------------
template <int MODE>
__device__ __forceinline__
void gemm_core(const float* __restrict__ A,
               const float* __restrict__ W, const float* __restrict__ bias,
               float* __restrict__ C, int mblk, int nblk, float* smem)
{
    float* sA = smem;                    // [STAGES][BM][LDA]
    float* sB = smem + STAGES * A_STG;   // [STAGES][BK][LDB]
    const uint32_t saB = (uint32_t)__cvta_generic_to_shared(sA);
    const uint32_t sbB = (uint32_t)__cvta_generic_to_shared(sB);

    const int tid  = threadIdx.x;
    const int lane = tid & 31;
    const int w    = tid >> 5;
    const int g    = lane >> 2;
    const int t4   = lane & 3;
    const int wm   = (w >> 2) * 64;
    const int wn   = (w & 3) * 32;

    float acc[4][4][4];
    #pragma unroll
    for (int i = 0; i < 4; i++)
        #pragma unroll
        for (int j = 0; j < 4; j++)
            #pragma unroll
            for (int r = 0; r < 4; r++) acc[i][j][r] = 0.f;

    auto ISSUE = [&](int stage, int bk) {
        const int k0 = bk * BK;
        #pragma unroll
        for (int c = 0; c < 2; c++) {
            const int ch = tid + c * 256;
            const int arow = ch >> 2, akp = (ch & 3) * 4;
            cp_async16(saB + (uint32_t)(stage * A_STG + arow * LDA + akp) * 4,
                       A + (size_t)(mblk + arow) * CIN + k0 + akp);
            const int brow = ch >> 5, bcol = (ch & 31) * 4;
            cp_async16(sbB + (uint32_t)(stage * B_STG + brow * LDB + bcol) * 4,
                       W + (size_t)(k0 + brow) * HID + nblk + bcol);
        }
        CP_COMMIT();
    };

    auto COMP = [&](int stage) {
        const float* a0 = sA + stage * A_STG;
        const float* b0 = sB + stage * B_STG;
        #pragma unroll
        for (int s = 0; s < 2; s++) {
            const int kb = s * 8;
            uint32_t af[4][4], bf[4][2];
            #pragma unroll
            for (int mt = 0; mt < 4; mt++) {
                const int m = wm + mt * 16 + g;
                af[mt][0] = f2tf32(a0[(m    ) * LDA + kb + t4    ]);
                af[mt][1] = f2tf32(a0[(m + 8) * LDA + kb + t4    ]);
                af[mt][2] = f2tf32(a0[(m    ) * LDA + kb + t4 + 4]);
                af[mt][3] = f2tf32(a0[(m + 8) * LDA + kb + t4 + 4]);
            }
            #pragma unroll
            for (int nt = 0; nt < 4; nt++) {
                const int n = wn + nt * 8 + g;
                bf[nt][0] = f2tf32(b0[(kb + t4    ) * LDB + n]);
                bf[nt][1] = f2tf32(b0[(kb + t4 + 4) * LDB + n]);
            }
            #pragma unroll
            for (int mt = 0; mt < 4; mt++)
                #pragma unroll
                for (int nt = 0; nt < 4; nt++)
                    mma1688(acc[mt][nt], af[mt], bf[nt]);
        }
    };

    constexpr int NIT = CIN / BK;   // 16
    ISSUE(0, 0);
    ISSUE(1, 1);

    for (int bk = 0; bk < NIT; bk++) {
        if (bk < NIT - 1) { CP_WAIT(1); } else { CP_WAIT(0); }
        __syncthreads();
        if (bk + 2 < NIT) ISSUE((bk + 2) % STAGES, bk + 2);
        COMP(bk % STAGES);
    }

    #pragma unroll
    for (int mt = 0; mt < 4; mt++) {
        const int row = mblk + wm + mt * 16 + g;
        #pragma unroll
        for (int nt = 0; nt < 4; nt++) {
            const int col = nblk + wn + nt * 8 + 2 * t4;
            float r0 = acc[mt][nt][0], r1 = acc[mt][nt][1];
            float r2 = acc[mt][nt][2], r3 = acc[mt][nt][3];
            if (MODE == 1) {
                r0 *= QSCALE; r1 *= QSCALE; r2 *= QSCALE; r3 *= QSCALE;
            } else if (MODE == 2) {
                r0 = 1.f / (1.f + __expf(-(r0 + bias[col])));
                r1 = 1.f / (1.f + __expf(-(r1 + bias[col + 1])));
                r2 = 1.f / (1.f + __expf(-(r2 + bias[col])));
                r3 = 1.f / (1.f + __expf(-(r3 + bias[col + 1])));
            } else if (MODE == 3) {
                r0 += bias[col]; r1 += bias[col + 1];
                r2 += bias[col]; r3 += bias[col + 1];
            }
            *(float2*)(C + (size_t)row * HID + col)       = make_float2(r0, r1);
            *(float2*)(C + (size_t)(row + 8) * HID + col) = make_float2(r2, r3);
        }
    }
}

// Batched projection: blockIdx.z selects {q, k, v, gate}
__global__ __launch_bounds__(256, 2)
void gemm_proj4(const float* __restrict__ q_x, const float* __restrict__ k_x,
                const float* __restrict__ v_x,
                const float* __restrict__ wq, const float* __restrict__ wk,
                const float* __restrict__ wv, const float* __restrict__ wg,
                const float* __restrict__ bg,
                float* __restrict__ oq, float* __restrict__ ok,
                float* __restrict__ ov, float* __restrict__ og)
{
    extern __shared__ float sgm[];
    const int z    = blockIdx.z;
    const int mblk = blockIdx.x * BM;
    const int nblk = blockIdx.y * BN;
    switch (z) {
    case 0: gemm_core<1>(q_x, wq, nullptr, oq, mblk, nblk, sgm); break;
    case 1: gemm_core<0>(k_x, wk, nullptr, ok, mblk, nblk, sgm); break;
    case 2: gemm_core<0>(v_x, wv, nullptr, ov, mblk, nblk, sgm); break;
    default: gemm_core<2>(q_x, wg, bg,     og, mblk, nblk, sgm); break;
    }
}

// Output projection (input already gated by attention epilogue)
__global__ __launch_bounds__(256, 2)
void gemm_out(const float* __restrict__ A,
              const float* __restrict__ W, const float* __restrict__ bias,
              float* __restrict__ C)
{
    extern __shared__ float sgm[];
    gemm_core<3>(A, W, bias, C, blockIdx.x * BM, blockIdx.y * BN, sgm);
}

// ---------------------------------------------------------------------------
// Tensor-core attention. One CTA = 128 q-rows of one (n, h); 256 thr, 8 warps.
// K staged in 4 chunks of 128 keys; softmax in 32-key passes (3 CTAs/SM).
// Gating (o *= sigmoid(...)) fused into the O-store epilogue.
// ---------------------------------------------------------------------------
namespace {
constexpr int AW_Q  = 0;                 // Qs [32][136] u32 (tf32)
constexpr int AW_K  = AW_Q + 32 * LDP;   // Ks [32][136]
constexpr int AW_V  = AW_K + 32 * LDP;   // Vs [128][40]
constexpr int AW_BM = AW_V + 128 * 40;   // bms [512] (float)
constexpr int ATTN_SMEM = (AW_BM + 512) * 4;   // 57344 B
}

__global__ __launch_bounds__(256, 3)
void attn_tc(const float* __restrict__ q, const float* __restrict__ kin,
             const float* __restrict__ vin, const float* __restrict__ bmask,
             const float* __restrict__ bp, const float* __restrict__ gate,
             float* __restrict__ o)
{
    extern __shared__ uint32_t su[];
    uint32_t* Qs = su + AW_Q;
    uint32_t* Ks = su + AW_K;
    uint32_t* Vs = su + AW_V;
    float*    bms = (float*)(su + AW_BM);

    const int qt = blockIdx.x;   // 0..3
    const int h  = blockIdx.y;   // 0..7
    const int n  = blockIdx.z;   // 0..63
    const int tid  = threadIdx.x;
    const int lane = tid & 31;
    const int w    = tid >> 5;
    const int g    = lane >> 2;
    const int t4   = lane & 3;
    const int m0   = w * 16 + g;

    // ---- load Q tile (pre-scaled by LOG2E; QSCALE applied upstream)
    {
        const int qrow = tid >> 1;
        const int c0   = (tid & 1) * 16;
        const float* src = q + ((size_t)n * QD + qt * 128 + qrow) * HID + h * CH + c0;
        #pragma unroll
        for (int i = 0; i < 16; i += 4) {
            float4 v = *(const float4*)(src + i);
            Qs[(c0 + i + 0) * LDP + qrow] = f2tf32(v.x * LOG2E);
            Qs[(c0 + i + 1) * LDP + qrow] = f2tf32(v.y * LOG2E);
            Qs[(c0 + i + 2) * LDP + qrow] = f2tf32(v.z * LOG2E);
            Qs[(c0 + i + 3) * LDP + qrow] = f2tf32(v.w * LOG2E);
        }
        for (int i = tid; i < KD; i += 256)
            bms[i] = bmask[(size_t)n * KD + i] * LOG2E;
    }

    float mrow0 = -1e30f, mrow1 = -1e30f, lrow0 = 0.f, lrow1 = 0.f;
    float oacc[4][4];
    #pragma unroll
    for (int nt = 0; nt < 4; nt++)
        #pragma unroll
        for (int r = 0; r < 4; r++) oacc[nt][r] = 0.f;

    const int srcA = 4 * g + (t4 >> 1);
    const int srcB = srcA + 2;
    const bool podd = (t4 & 1);

    for (int kc = 0; kc < 4; kc++) {
        __syncthreads();   // prior consumers done with Ks/Vs (also covers Q/bms init)
        // ---- stage K, V chunk (tf32)
        {
            const int kl   = tid & 127;
            const int half = (tid >> 7) * 16;
            const float* ksrc = kin + ((size_t)n * KD + kc * 128 + kl) * HID + h * CH + half;
            const float* vsrc = vin + ((size_t)n * KD + kc * 128 + kl) * HID + h * CH + half;
            #pragma unroll
            for (int i = 0; i < 16; i += 4) {
                float4 kv = *(const float4*)(ksrc + i);
                Ks[(half + i + 0) * LDP + kl] = f2tf32(kv.x);
                Ks[(half + i + 1) * LDP + kl] = f2tf32(kv.y);
                Ks[(half + i + 2) * LDP + kl] = f2tf32(kv.z);
                Ks[(half + i + 3) * LDP + kl] = f2tf32(kv.w);
                float4 vv = *(const float4*)(vsrc + i);
                Vs[kl * 40 + half + i + 0] = f2tf32(vv.x);
                Vs[kl * 40 + half + i + 1] = f2tf32(vv.y);
                Vs[kl * 40 + half + i + 2] = f2tf32(vv.z);
                Vs[kl * 40 + half + i + 3] = f2tf32(vv.w);
            }
        }
        __syncthreads();

        #pragma unroll
        for (int qtr = 0; qtr < 4; qtr++) {
            const int kb = qtr * 32;     // key offset within chunk

            // ---- Q fragments (reloaded per pass; live only in S-phase)
            uint32_t qf[4][4];
            #pragma unroll
            for (int ks = 0; ks < 4; ks++) {
                qf[ks][0] = Qs[(ks * 8 + t4    ) * LDP + m0];
                qf[ks][1] = Qs[(ks * 8 + t4    ) * LDP + m0 + 8];
                qf[ks][2] = Qs[(ks * 8 + t4 + 4) * LDP + m0];
                qf[ks][3] = Qs[(ks * 8 + t4 + 4) * LDP + m0 + 8];
            }

            // ---- S = Q @ K^T  (16 q-rows x 32 keys)
            float s[4][4];
            #pragma unroll
            for (int nt = 0; nt < 4; nt++) {
                s[nt][0] = s[nt][1] = s[nt][2] = s[nt][3] = 0.f;
                #pragma unroll
                for (int ks = 0; ks < 4; ks++) {
                    uint32_t bf[2];
                    bf[0] = Ks[(ks * 8 + t4    ) * LDP + kb + nt * 8 + g];
                    bf[1] = Ks[(ks * 8 + t4 + 4) * LDP + kb + nt * 8 + g];
                    mma1688(s[nt], qf[ks], bf);
                }
            }

            // ---- biases
            const float* bpr0 = bp + ((size_t)h * QD + qt * 128 + w * 16 + g) * KD
                              + kc * 128 + kb;
            const float* bpr1 = bpr0 + 8 * KD;
            #pragma unroll
            for (int nt = 0; nt < 4; nt++) {
                const int c = nt * 8 + 2 * t4;
                const float2 b0 = *(const float2*)(bpr0 + c);
                const float2 b1 = *(const float2*)(bpr1 + c);
                const float bm0 = bms[kc * 128 + kb + c];
                const float bm1 = bms[kc * 128 + kb + c + 1];
                s[nt][0] = fmaf(b0.x, LOG2E, s[nt][0] + bm0);
                s[nt][1] = fmaf(b0.y, LOG2E, s[nt][1] + bm1);
                s[nt][2] = fmaf(b1.x, LOG2E, s[nt][2] + bm0);
                s[nt][3] = fmaf(b1.y, LOG2E, s[nt][3] + bm1);
            }

            // ---- row max (local cols, then t4 quad)
            float mx0 = -1e30f, mx1 = -1e30f;
            #pragma unroll
            for (int nt = 0; nt < 4; nt++) {
                mx0 = fmaxf(mx0, fmaxf(s[nt][0], s[nt][1]));
                mx1 = fmaxf(mx1, fmaxf(s[nt][2], s[nt][3]));
            }
            mx0 = fmaxf(mx0, __shfl_xor_sync(0xffffffffu, mx0, 1));
            mx0 = fmaxf(mx0, __shfl_xor_sync(0xffffffffu, mx0, 2));
            mx1 = fmaxf(mx1, __shfl_xor_sync(0xffffffffu, mx1, 1));
            mx1 = fmaxf(mx1, __shfl_xor_sync(0xffffffffu, mx1, 2));

            const float mn0 = fmaxf(mrow0, mx0);
            const float mn1 = fmaxf(mrow1, mx1);
            const float cr0 = exp2f(mrow0 - mn0);
            const float cr1 = exp2f(mrow1 - mn1);
            mrow0 = mn0; mrow1 = mn1;
            lrow0 *= cr0; lrow1 *= cr1;
            #pragma unroll
            for (int nt = 0; nt < 4; nt++) {
                oacc[nt][0] *= cr0; oacc[nt][1] *= cr0;
                oacc[nt][2] *= cr1; oacc[nt][3] *= cr1;
            }

            // ---- P = exp2(s - m), accumulate row sums (in place)
            #pragma unroll
            for (int nt = 0; nt < 4; nt++) {
                s[nt][0] = exp2f(s[nt][0] - mrow0);
                s[nt][1] = exp2f(s[nt][1] - mrow0);
                s[nt][2] = exp2f(s[nt][2] - mrow1);
                s[nt][3] = exp2f(s[nt][3] - mrow1);
                lrow0 += s[nt][0] + s[nt][1];
                lrow1 += s[nt][2] + s[nt][3];
            }

            // ---- O += P @ V : A-fragment via quad shfl (no smem)
            #pragma unroll
            for (int ks = 0; ks < 4; ks++) {
                const float x0 = __shfl_sync(0xffffffffu, s[ks][0], srcA);
                const float x1 = __shfl_sync(0xffffffffu, s[ks][1], srcA);
                const float y0 = __shfl_sync(0xffffffffu, s[ks][2], srcA);
                const float y1 = __shfl_sync(0xffffffffu, s[ks][3], srcA);
                const float z0 = __shfl_sync(0xffffffffu, s[ks][0], srcB);
                const float z1 = __shfl_sync(0xffffffffu, s[ks][1], srcB);
                const float u0 = __shfl_sync(0xffffffffu, s[ks][2], srcB);
                const float u1 = __shfl_sync(0xffffffffu, s[ks][3], srcB);
                uint32_t pf[4];
                pf[0] = f2tf32(podd ? x1 : x0);
                pf[1] = f2tf32(podd ? y1 : y0);
                pf[2] = f2tf32(podd ? z1 : z0);
                pf[3] = f2tf32(podd ? u1 : u0);
                const int krow = kb + ks * 8;
                #pragma unroll
                for (int nt = 0; nt < 4; nt++) {
                    uint32_t vf[2];
                    vf[0] = Vs[(krow + t4    ) * 40 + nt * 8 + g];
                    vf[1] = Vs[(krow + t4 + 4) * 40 + nt * 8 + g];
                    mma1688(oacc[nt], pf, vf);
                }
            }
        }
    }

    // ---- finalize: normalize, gate, store
    lrow0 += __shfl_xor_sync(0xffffffffu, lrow0, 1);
    lrow0 += __shfl_xor_sync(0xffffffffu, lrow0, 2);
    lrow1 += __shfl_xor_sync(0xffffffffu, lrow1, 1);
    lrow1 += __shfl_xor_sync(0xffffffffu, lrow1, 2);
    const float inv0 = 1.f / lrow0;
    const float inv1 = 1.f / lrow1;

    const size_t rbase = ((size_t)n * QD + qt * 128 + w * 16 + g) * HID + h * CH;
    float*       ob0 = o + rbase;
    float*       ob1 = ob0 + 8 * HID;
    const float* gb0 = gate + rbase;
    const float* gb1 = gb0 + 8 * HID;
    #pragma unroll
    for (int nt = 0; nt < 4; nt++) {
        const int c = nt * 8 + 2 * t4;
        const float2 gg0 = *(const float2*)(gb0 + c);
        const float2 gg1 = *(const float2*)(gb1 + c);
        *(float2*)(ob0 + c) = make_float2(oacc[nt][0] * inv0 * gg0.x,
                                          oacc[nt][1] * inv0 * gg0.y);
        *(float2*)(ob1 + c) = make_float2(oacc[nt][2] * inv1 * gg1.x,
                                          oacc[nt][3] * inv1 * gg1.y);
    }
}

// ---------------------------------------------------------------------------
extern "C" void kernel_launch(void* const* d_in, const int* in_sizes, int n_in,
                              void* d_out, int out_size)
{
    const float* q_x       = (const float*)d_in[0];
    const float* k_x       = (const float*)d_in[1];
    const float* v_x       = (const float*)d_in[2];
    const float* bias_mask = (const float*)d_in[3];
    const float* bias_pair = (const float*)d_in[4];
    const float* wq        = (const float*)d_in[5];
    const float* wk        = (const float*)d_in[6];
    const float* wv        = (const float*)d_in[7];
    const float* wg        = (const float*)d_in[8];
    const float* bg        = (const float*)d_in[9];
    const float* wo        = (const float*)d_in[10];
    const float* bo        = (const float*)d_in[11];
    float* out             = (float*)d_out;

    float *pq, *pk, *pv, *pg, *po;
    cudaGetSymbolAddress((void**)&pq, g_q);
    cudaGetSymbolAddress((void**)&pk, g_k);
    cudaGetSymbolAddress((void**)&pv, g_v);
    cudaGetSymbolAddress((void**)&pg, g_g);
    cudaGetSymbolAddress((void**)&po, g_o);

    static bool attr_set = false;
    if (!attr_set) {
        cudaFuncSetAttribute(attn_tc, cudaFuncAttributeMaxDynamicSharedMemorySize,
                             ATTN_SMEM);
        cudaFuncSetAttribute(gemm_proj4, cudaFuncAttributeMaxDynamicSharedMemorySize,
                             GEMM_SMEM);
        cudaFuncSetAttribute(gemm_out, cudaFuncAttributeMaxDynamicSharedMemorySize,
                             GEMM_SMEM);
        attr_set = true;
    }

    // batched input projections (q, k, v, gate)
    {
        dim3 grid(MTOT / BM, HID / BN, 4), blk(256);
        gemm_proj4<<<grid, blk, GEMM_SMEM>>>(q_x, k_x, v_x, wq, wk, wv, wg, bg,
                                             pq, pk, pv, pg);
    }

    // tensor-core attention (gating fused into epilogue)
    {
        dim3 grid(QD / 128, HEADS, NRES), blk(256);
        attn_tc<<<grid, blk, ATTN_SMEM>>>(pq, pk, pv, bias_mask, bias_pair, pg, po);
    }

    // output projection -> d_out
    {
        dim3 grid(MTOT / BM, HID / BN), blk(256);
        gemm_out<<<grid, blk, GEMM_SMEM>>>(po, wo, bo, out);
    }
}

// round 9
// speedup vs baseline: 3.0260x; 1.0451x over previous
#include <cuda_runtime.h>
#include <math.h>
#include <stdint.h>

// ---------------------------------------------------------------------------
// Problem constants
// ---------------------------------------------------------------------------
namespace {
constexpr int NRES  = 64;
constexpr int QD    = 512;
constexpr int KD    = 512;
constexpr int CIN   = 256;
constexpr int HEADS = 8;
constexpr int CH    = 32;
constexpr int HID   = 256;
constexpr int MTOT  = NRES * QD;                 // 32768
constexpr float QSCALE = 0.17677669529663687f;   // 1/sqrt(32)
constexpr float LOG2E  = 1.4426950408889634f;

// GEMM tiling
constexpr int BM = 128, BN = 128, BK = 16;
constexpr int LDA    = 20;                       // A row stride (floats)
constexpr int LDB    = 136;                      // B row stride (floats)
constexpr int STAGES = 3;
constexpr int A_STG  = BM * LDA;                 // 2560 floats
constexpr int B_STG  = BK * LDB;                 // 2176 floats
constexpr int GEMM_SMEM = STAGES * (A_STG + B_STG) * 4;  // 56832 B

// Attention smem layout (u32 words)
constexpr int LDQ = 36;                          // Qs [m 128][ch 32 + pad]
constexpr int LDK = 36;                          // Ks [key 128][ch 32 + pad]
constexpr int LDV = 132;                         // Vs [ch 32][key 128 + pad]
constexpr int AW_Q  = 0;
constexpr int AW_K  = AW_Q + 128 * LDQ;          // 4608
constexpr int AW_V  = AW_K + 128 * LDK;          // 9216
constexpr int AW_BM = AW_V + 32 * LDV;           // 13440
constexpr int ATTN_SMEM = (AW_BM + 512) * 4;     // 55808 B
}

// Scratch (static device globals; no runtime allocation)
__device__ float g_q  [(size_t)MTOT * HID];
__device__ float g_k  [(size_t)MTOT * HID];
__device__ float g_v  [(size_t)MTOT * HID];
__device__ float g_g  [(size_t)MTOT * HID];
__device__ float g_o  [(size_t)MTOT * HID];

// ---------------------------------------------------------------------------
// helpers
// ---------------------------------------------------------------------------
__device__ __forceinline__ uint32_t f2tf32(float x) {
    uint32_t u;
    asm("cvt.rna.tf32.f32 %0, %1;" : "=r"(u) : "f"(x));
    return u;
}
__device__ __forceinline__ uint32_t u2tf32(uint32_t x) {
    uint32_t u;
    asm("cvt.rna.tf32.f32 %0, %1;" : "=r"(u) : "f"(__uint_as_float(x)));
    return u;
}

// D += A * B  (m16n8k8, tf32 in, f32 accum)
__device__ __forceinline__ void mma1688(float* c, const uint32_t* a, const uint32_t* b) {
    asm volatile(
        "mma.sync.aligned.m16n8k8.row.col.f32.tf32.tf32.f32 "
        "{%0,%1,%2,%3}, {%4,%5,%6,%7}, {%8,%9}, {%0,%1,%2,%3};"
        : "+f"(c[0]), "+f"(c[1]), "+f"(c[2]), "+f"(c[3])
        : "r"(a[0]), "r"(a[1]), "r"(a[2]), "r"(a[3]), "r"(b[0]), "r"(b[1]));
}

// ldmatrix x4 (b16 view of fp32 tiles): 4 regs = one 16x8-f32 fragment group
__device__ __forceinline__ void ldmx4(uint32_t* r, uint32_t addr) {
    asm volatile("ldmatrix.sync.aligned.m8n8.x4.shared.b16 {%0,%1,%2,%3}, [%4];"
                 : "=r"(r[0]), "=r"(r[1]), "=r"(r[2]), "=r"(r[3]) : "r"(addr));
}

__device__ __forceinline__ void cp_async16(uint32_t smem_addr, const void* gptr) {
    asm volatile("cp.async.ca.shared.global [%0], [%1], 16;"
                 :: "r"(smem_addr), "l"(gptr));
}
#define CP_COMMIT() asm volatile("cp.async.commit_group;" ::: "memory")
#define CP_WAIT(n)  asm volatile("cp.async.wait_group %0;" :: "n"(n) : "memory")

// ---------------------------------------------------------------------------
// tf32 mma.sync GEMM core, cp.async 3-stage pipeline, ldmatrix A-fragments.
// MODE 0: plain  1: *QSCALE  2: sigmoid(x+bias)  3: +bias
// ---------------------------------------------------------------------------
template <int MODE>
__device__ __forceinline__
void gemm_core(const float* __restrict__ A,
               const float* __restrict__ W, const float* __restrict__ bias,
               float* __restrict__ C, int mblk, int nblk, float* smem)
{
    float* sA = smem;                    // [STAGES][BM][LDA]
    float* sB = smem + STAGES * A_STG;   // [STAGES][BK][LDB]
    const uint32_t saB = (uint32_t)__cvta_generic_to_shared(sA);
    const uint32_t sbB = (uint32_t)__cvta_generic_to_shared(sB);

    const int tid  = threadIdx.x;
    const int lane = tid & 31;
    const int w    = tid >> 5;
    const int g    = lane >> 2;
    const int t4   = lane & 3;
    const int wm   = (w >> 2) * 64;
    const int wn   = (w & 3) * 32;
    const int r8   = (lane & 7) + (lane & 8);
    const int c4   = (lane & 16) >> 2;

    // per-lane ldmatrix base for A fragments (bytes, within stage 0)
    const uint32_t a_ldm = saB + (uint32_t)((wm + r8) * LDA + c4) * 4;

    float acc[4][4][4];
    #pragma unroll
    for (int i = 0; i < 4; i++)
        #pragma unroll
        for (int j = 0; j < 4; j++)
            #pragma unroll
            for (int r = 0; r < 4; r++) acc[i][j][r] = 0.f;

    auto ISSUE = [&](int stage, int bk) {
        const int k0 = bk * BK;
        #pragma unroll
        for (int c = 0; c < 2; c++) {
            const int ch = tid + c * 256;
            const int arow = ch >> 2, akp = (ch & 3) * 4;
            cp_async16(saB + (uint32_t)(stage * A_STG + arow * LDA + akp) * 4,
                       A + (size_t)(mblk + arow) * CIN + k0 + akp);
            const int brow = ch >> 5, bcol = (ch & 31) * 4;
            cp_async16(sbB + (uint32_t)(stage * B_STG + brow * LDB + bcol) * 4,
                       W + (size_t)(k0 + brow) * HID + nblk + bcol);
        }
        CP_COMMIT();
    };

    auto COMP = [&](int stage) {
        const float* b0 = sB + stage * B_STG;
        const uint32_t a0 = a_ldm + (uint32_t)(stage * A_STG) * 4;
        #pragma unroll
        for (int s = 0; s < 2; s++) {
            const int kb = s * 8;
            uint32_t af[4][4], bf[4][2];
            #pragma unroll
            for (int mt = 0; mt < 4; mt++) {
                ldmx4(af[mt], a0 + (uint32_t)(mt * 16 * LDA + kb) * 4);
                af[mt][0] = u2tf32(af[mt][0]);
                af[mt][1] = u2tf32(af[mt][1]);
                af[mt][2] = u2tf32(af[mt][2]);
                af[mt][3] = u2tf32(af[mt][3]);
            }
            #pragma unroll
            for (int nt = 0; nt < 4; nt++) {
                const int n = wn + nt * 8 + g;
                bf[nt][0] = f2tf32(b0[(kb + t4    ) * LDB + n]);
                bf[nt][1] = f2tf32(b0[(kb + t4 + 4) * LDB + n]);
            }
            #pragma unroll
            for (int mt = 0; mt < 4; mt++)
                #pragma unroll
                for (int nt = 0; nt < 4; nt++)
                    mma1688(acc[mt][nt], af[mt], bf[nt]);
        }
    };

    constexpr int NIT = CIN / BK;   // 16
    ISSUE(0, 0);
    ISSUE(1, 1);

    for (int bk = 0; bk < NIT; bk++) {
        if (bk < NIT - 1) { CP_WAIT(1); } else { CP_WAIT(0); }
        __syncthreads();
        if (bk + 2 < NIT) ISSUE((bk + 2) % STAGES, bk + 2);
        COMP(bk % STAGES);
    }

    #pragma unroll
    for (int mt = 0; mt < 4; mt++) {
        const int row = mblk + wm + mt * 16 + g;
        #pragma unroll
        for (int nt = 0; nt < 4; nt++) {
            const int col = nblk + wn + nt * 8 + 2 * t4;
            float r0 = acc[mt][nt][0], r1 = acc[mt][nt][1];
            float r2 = acc[mt][nt][2], r3 = acc[mt][nt][3];
            if (MODE == 1) {
                r0 *= QSCALE; r1 *= QSCALE; r2 *= QSCALE; r3 *= QSCALE;
            } else if (MODE == 2) {
                r0 = 1.f / (1.f + __expf(-(r0 + bias[col])));
                r1 = 1.f / (1.f + __expf(-(r1 + bias[col + 1])));
                r2 = 1.f / (1.f + __expf(-(r2 + bias[col])));
                r3 = 1.f / (1.f + __expf(-(r3 + bias[col + 1])));
            } else if (MODE == 3) {
                r0 += bias[col]; r1 += bias[col + 1];
                r2 += bias[col]; r3 += bias[col + 1];
            }
            *(float2*)(C + (size_t)row * HID + col)       = make_float2(r0, r1);
            *(float2*)(C + (size_t)(row + 8) * HID + col) = make_float2(r2, r3);
        }
    }
}

// Batched projection: blockIdx.z selects {q, k, v, gate}
__global__ __launch_bounds__(256, 2)
void gemm_proj4(const float* __restrict__ q_x, const float* __restrict__ k_x,
                const float* __restrict__ v_x,
                const float* __restrict__ wq, const float* __restrict__ wk,
                const float* __restrict__ wv, const float* __restrict__ wg,
                const float* __restrict__ bg,
                float* __restrict__ oq, float* __restrict__ ok,
                float* __restrict__ ov, float* __restrict__ og)
{
    extern __shared__ float sgm[];
    const int z    = blockIdx.z;
    const int mblk = blockIdx.x * BM;
    const int nblk = blockIdx.y * BN;
    switch (z) {
    case 0: gemm_core<1>(q_x, wq, nullptr, oq, mblk, nblk, sgm); break;
    case 1: gemm_core<0>(k_x, wk, nullptr, ok, mblk, nblk, sgm); break;
    case 2: gemm_core<0>(v_x, wv, nullptr, ov, mblk, nblk, sgm); break;
    default: gemm_core<2>(q_x, wg, bg,     og, mblk, nblk, sgm); break;
    }
}

__global__ __launch_bounds__(256, 2)
void gemm_out(const float* __restrict__ A,
              const float* __restrict__ W, const float* __restrict__ bias,
              float* __restrict__ C)
{
    extern __shared__ float sgm[];
    gemm_core<3>(A, W, bias, C, blockIdx.x * BM, blockIdx.y * BN, sgm);
}

// ---------------------------------------------------------------------------
// Tensor-core attention, all fragments via ldmatrix.
// One CTA = 128 q-rows of one (n, h); 256 thr, 8 warps; 32-key passes.
// Layouts: Qs[m][ch], Ks[key][ch], Vs[ch][key] (tf32-valued words).
// ---------------------------------------------------------------------------
__global__ __launch_bounds__(256, 3)
void attn_tc(const float* __restrict__ q, const float* __restrict__ kin,
             const float* __restrict__ vin, const float* __restrict__ bmask,
             const float* __restrict__ bp, const float* __restrict__ gate,
             float* __restrict__ o)
{
    extern __shared__ uint32_t su[];
    uint32_t* Qs = su + AW_Q;
    uint32_t* Ks = su + AW_K;
    uint32_t* Vs = su + AW_V;
    float*    bms = (float*)(su + AW_BM);

    const uint32_t s_u32 = (uint32_t)__cvta_generic_to_shared(su);
    const uint32_t qs_b  = s_u32 + AW_Q * 4;
    const uint32_t ks_b  = s_u32 + AW_K * 4;
    const uint32_t vs_b  = s_u32 + AW_V * 4;

    const int qt = blockIdx.x;   // 0..3
    const int h  = blockIdx.y;   // 0..7
    const int n  = blockIdx.z;   // 0..63
    const int tid  = threadIdx.x;
    const int lane = tid & 31;
    const int w    = tid >> 5;
    const int g    = lane >> 2;
    const int t4   = lane & 3;
    const int r8   = (lane & 7) + (lane & 8);
    const int c4   = (lane & 16) >> 2;
    const int l7   = lane & 7;
    const int l3x4 = (lane >> 3) * 4;

    // ldmatrix per-lane bases (bytes)
    const uint32_t qf_base = qs_b + (uint32_t)((w * 16 + r8) * LDQ + c4) * 4;
    const uint32_t kf_base = ks_b + (uint32_t)(l7 * LDK + l3x4) * 4;
    const uint32_t vf_base = vs_b + (uint32_t)(l7 * LDV + l3x4) * 4;

    // ---- load Q tile (Qs[m][ch], tf32, pre-scaled by LOG2E)
    {
        const int qrow = tid >> 1;
        const int c0   = (tid & 1) * 16;
        const float* src = q + ((size_t)n * QD + qt * 128 + qrow) * HID + h * CH + c0;
        #pragma unroll
        for (int i = 0; i < 16; i += 4) {
            float4 v = *(const float4*)(src + i);
            uint4 u;
            u.x = f2tf32(v.x * LOG2E); u.y = f2tf32(v.y * LOG2E);
            u.z = f2tf32(v.z * LOG2E); u.w = f2tf32(v.w * LOG2E);
            *(uint4*)(Qs + qrow * LDQ + c0 + i) = u;
        }
        for (int i = tid; i < KD; i += 256)
            bms[i] = bmask[(size_t)n * KD + i] * LOG2E;
    }

    float mrow0 = -1e30f, mrow1 = -1e30f, lrow0 = 0.f, lrow1 = 0.f;
    float oacc[4][4];
    #pragma unroll
    for (int nt = 0; nt < 4; nt++)
        #pragma unroll
        for (int r = 0; r < 4; r++) oacc[nt][r] = 0.f;

    const int srcA = 4 * g + (t4 >> 1);
    const int srcB = srcA + 2;
    const bool podd = (t4 & 1);

    for (int kc = 0; kc < 4; kc++) {
        __syncthreads();   // prior consumers done with Ks/Vs (also covers Q/bms init)
        // ---- stage K (Ks[key][ch], vectorized) and V (Vs[ch][key], scatter)
        {
            const int kl   = tid & 127;
            const int half = (tid >> 7) * 16;
            const float* ksrc = kin + ((size_t)n * KD + kc * 128 + kl) * HID + h * CH + half;
            const float* vsrc = vin + ((size_t)n * KD + kc * 128 + kl) * HID + h * CH + half;
            #pragma unroll
            for (int i = 0; i < 16; i += 4) {
                float4 kv = *(const float4*)(ksrc + i);
                uint4 u;
                u.x = f2tf32(kv.x); u.y = f2tf32(kv.y);
                u.z = f2tf32(kv.z); u.w = f2tf32(kv.w);
                *(uint4*)(Ks + kl * LDK + half + i) = u;
                float4 vv = *(const float4*)(vsrc + i);
                Vs[(half + i + 0) * LDV + kl] = f2tf32(vv.x);
                Vs[(half + i + 1) * LDV + kl] = f2tf32(vv.y);
                Vs[(half + i + 2) * LDV + kl] = f2tf32(vv.z);
                Vs[(half + i + 3) * LDV + kl] = f2tf32(vv.w);
            }
        }
        __syncthreads();

        #pragma unroll
        for (int qtr = 0; qtr < 4; qtr++) {
            const int kb = qtr * 32;     // key offset within chunk

            // ---- Q fragments (4 ldmatrix; live only in S-phase)
            uint32_t qfr[4][4];
            #pragma unroll
            for (int ks = 0; ks < 4; ks++)
                ldmx4(qfr[ks], qf_base + ks * 32);

            // ---- S = Q @ K^T  (16 q-rows x 32 keys)
            float s[4][4];
            #pragma unroll
            for (int nt = 0; nt < 4; nt++) {
                s[nt][0] = s[nt][1] = s[nt][2] = s[nt][3] = 0.f;
                const uint32_t ka = kf_base + (uint32_t)((kb + nt * 8) * LDK) * 4;
                uint32_t kk[4];
                ldmx4(kk, ka);            // ch 0-15: ks0 {b0,b1}, ks1 {b0,b1}
                mma1688(s[nt], qfr[0], kk);
                mma1688(s[nt], qfr[1], kk + 2);
                ldmx4(kk, ka + 64);       // ch 16-31
                mma1688(s[nt], qfr[2], kk);
                mma1688(s[nt], qfr[3], kk + 2);
            }

            // ---- biases
            const float* bpr0 = bp + ((size_t)h * QD + qt * 128 + w * 16 + g) * KD
                              + kc * 128 + kb;
            const float* bpr1 = bpr0 + 8 * KD;
            #pragma unroll
            for (int nt = 0; nt < 4; nt++) {
                const int c = nt * 8 + 2 * t4;
                const float2 b0 = *(const float2*)(bpr0 + c);
                const float2 b1 = *(const float2*)(bpr1 + c);
                const float bm0 = bms[kc * 128 + kb + c];
                const float bm1 = bms[kc * 128 + kb + c + 1];
                s[nt][0] = fmaf(b0.x, LOG2E, s[nt][0] + bm0);
                s[nt][1] = fmaf(b0.y, LOG2E, s[nt][1] + bm1);
                s[nt][2] = fmaf(b1.x, LOG2E, s[nt][2] + bm0);
                s[nt][3] = fmaf(b1.y, LOG2E, s[nt][3] + bm1);
            }

            // ---- row max (local cols, then t4 quad)
            float mx0 = -1e30f, mx1 = -1e30f;
            #pragma unroll
            for (int nt = 0; nt < 4; nt++) {
                mx0 = fmaxf(mx0, fmaxf(s[nt][0], s[nt][1]));
                mx1 = fmaxf(mx1, fmaxf(s[nt][2], s[nt][3]));
            }
            mx0 = fmaxf(mx0, __shfl_xor_sync(0xffffffffu, mx0, 1));
            mx0 = fmaxf(mx0, __shfl_xor_sync(0xffffffffu, mx0, 2));
            mx1 = fmaxf(mx1, __shfl_xor_sync(0xffffffffu, mx1, 1));
            mx1 = fmaxf(mx1, __shfl_xor_sync(0xffffffffu, mx1, 2));

            const float mn0 = fmaxf(mrow0, mx0);
            const float mn1 = fmaxf(mrow1, mx1);
            const float cr0 = exp2f(mrow0 - mn0);
            const float cr1 = exp2f(mrow1 - mn1);
            mrow0 = mn0; mrow1 = mn1;
            lrow0 *= cr0; lrow1 *= cr1;
            #pragma unroll
            for (int nt = 0; nt < 4; nt++) {
                oacc[nt][0] *= cr0; oacc[nt][1] *= cr0;
                oacc[nt][2] *= cr1; oacc[nt][3] *= cr1;
            }

            // ---- P = exp2(s - m), accumulate row sums
            #pragma unroll
            for (int nt = 0; nt < 4; nt++) {
                s[nt][0] = exp2f(s[nt][0] - mrow0);
                s[nt][1] = exp2f(s[nt][1] - mrow0);
                s[nt][2] = exp2f(s[nt][2] - mrow1);
                s[nt][3] = exp2f(s[nt][3] - mrow1);
                lrow0 += s[nt][0] + s[nt][1];
                lrow1 += s[nt][2] + s[nt][3];
            }

            // ---- O += P @ V : P-frags via quad shfl, V-frags via ldmatrix
            #pragma unroll
            for (int h2 = 0; h2 < 2; h2++) {
                uint32_t pfA[4], pfB[4];
                #pragma unroll
                for (int e = 0; e < 2; e++) {
                    const int ks = h2 * 2 + e;
                    const float x0 = __shfl_sync(0xffffffffu, s[ks][0], srcA);
                    const float x1 = __shfl_sync(0xffffffffu, s[ks][1], srcA);
                    const float y0 = __shfl_sync(0xffffffffu, s[ks][2], srcA);
                    const float y1 = __shfl_sync(0xffffffffu, s[ks][3], srcA);
                    const float z0 = __shfl_sync(0xffffffffu, s[ks][0], srcB);
                    const float z1 = __shfl_sync(0xffffffffu, s[ks][1], srcB);
                    const float u0 = __shfl_sync(0xffffffffu, s[ks][2], srcB);
                    const float u1 = __shfl_sync(0xffffffffu, s[ks][3], srcB);
                    uint32_t* pf = e ? pfB : pfA;
                    pf[0] = f2tf32(podd ? x1 : x0);
                    pf[1] = f2tf32(podd ? y1 : y0);
                    pf[2] = f2tf32(podd ? z1 : z0);
                    pf[3] = f2tf32(podd ? u1 : u0);
                }
                #pragma unroll
                for (int nt = 0; nt < 4; nt++) {
                    uint32_t vv[4];
                    ldmx4(vv, vf_base + (uint32_t)(nt * 8 * LDV + kb + h2 * 16) * 4);
                    mma1688(oacc[nt], pfA, vv);      // keys kb+h2*16 .. +7
                    mma1688(oacc[nt], pfB, vv + 2);  // keys +8 .. +15
                }
            }
        }
    }

    // ---- finalize: normalize, gate, store
    lrow0 += __shfl_xor_sync(0xffffffffu, lrow0, 1);
    lrow0 += __shfl_xor_sync(0xffffffffu, lrow0, 2);
    lrow1 += __shfl_xor_sync(0xffffffffu, lrow1, 1);
    lrow1 += __shfl_xor_sync(0xffffffffu, lrow1, 2);
    const float inv0 = 1.f / lrow0;
    const float inv1 = 1.f / lrow1;

    const size_t rbase = ((size_t)n * QD + qt * 128 + w * 16 + g) * HID + h * CH;
    float*       ob0 = o + rbase;
    float*       ob1 = ob0 + 8 * HID;
    const float* gb0 = gate + rbase;
    const float* gb1 = gb0 + 8 * HID;
    #pragma unroll
    for (int nt = 0; nt < 4; nt++) {
        const int c = nt * 8 + 2 * t4;
        const float2 gg0 = *(const float2*)(gb0 + c);
        const float2 gg1 = *(const float2*)(gb1 + c);
        *(float2*)(ob0 + c) = make_float2(oacc[nt][0] * inv0 * gg0.x,
                                          oacc[nt][1] * inv0 * gg0.y);
        *(float2*)(ob1 + c) = make_float2(oacc[nt][2] * inv1 * gg1.x,
                                          oacc[nt][3] * inv1 * gg1.y);
    }
}

// ---------------------------------------------------------------------------
extern "C" void kernel_launch(void* const* d_in, const int* in_sizes, int n_in,
                              void* d_out, int out_size)
{
    const float* q_x       = (const float*)d_in[0];
    const float* k_x       = (const float*)d_in[1];
    const float* v_x       = (const float*)d_in[2];
    const float* bias_mask = (const float*)d_in[3];
    const float* bias_pair = (const float*)d_in[4];
    const float* wq        = (const float*)d_in[5];
    const float* wk        = (const float*)d_in[6];
    const float* wv        = (const float*)d_in[7];
    const float* wg        = (const float*)d_in[8];
    const float* bg        = (const float*)d_in[9];
    const float* wo        = (const float*)d_in[10];
    const float* bo        = (const float*)d_in[11];
    float* out             = (float*)d_out;

    float *pq, *pk, *pv, *pg, *po;
    cudaGetSymbolAddress((void**)&pq, g_q);
    cudaGetSymbolAddress((void**)&pk, g_k);
    cudaGetSymbolAddress((void**)&pv, g_v);
    cudaGetSymbolAddress((void**)&pg, g_g);
    cudaGetSymbolAddress((void**)&po, g_o);

    static bool attr_set = false;
    if (!attr_set) {
        cudaFuncSetAttribute(attn_tc, cudaFuncAttributeMaxDynamicSharedMemorySize,
                             ATTN_SMEM);
        cudaFuncSetAttribute(gemm_proj4, cudaFuncAttributeMaxDynamicSharedMemorySize,
                             GEMM_SMEM);
        cudaFuncSetAttribute(gemm_out, cudaFuncAttributeMaxDynamicSharedMemorySize,
                             GEMM_SMEM);
        attr_set = true;
    }

    // batched input projections (q, k, v, gate)
    {
        dim3 grid(MTOT / BM, HID / BN, 4), blk(256);
        gemm_proj4<<<grid, blk, GEMM_SMEM>>>(q_x, k_x, v_x, wq, wk, wv, wg, bg,
                                             pq, pk, pv, pg);
    }

    // tensor-core attention (gating fused into epilogue)
    {
        dim3 grid(QD / 128, HEADS, NRES), blk(256);
        attn_tc<<<grid, blk, ATTN_SMEM>>>(pq, pk, pv, bias_mask, bias_pair, pg, po);
    }

    // output projection -> d_out
    {
        dim3 grid(MTOT / BM, HID / BN), blk(256);
        gemm_out<<<grid, blk, GEMM_SMEM>>>(po, wo, bo, out);
    }
}